// round 5
// baseline (speedup 1.0000x reference)
#include <cuda_runtime.h>
#include <math.h>

#define TOKENS 1576
#define DMODEL 768
#define HID 3072
#define NHEAD 12
#define HD 64
#define NSEQ 197
#define BATCH 8
#define NEXP 8
#define NTASK 8
#define BH (BATCH*NHEAD)

#define FLAG_GELU 1
#define FLAG_ACC  2

// ---------------- scratch (device globals; no runtime allocation) ----------------
__device__ __align__(16) float g_ln[TOKENS*DMODEL];
__device__ __align__(16) float g_qkv[TOKENS*3*DMODEL];
__device__ __align__(16) float g_S[BH*NSEQ*NSEQ];
__device__ __align__(16) float g_attn[TOKENS*DMODEL];
__device__ __align__(16) float g_h[TOKENS*HID];
__device__ __align__(16) float g_x1[TOKENS*DMODEL];
__device__ __align__(16) float g_x2[TOKENS*DMODEL];
__device__ __align__(16) float g_x3[TOKENS*DMODEL];
__device__ __align__(16) float g_y[TOKENS*DMODEL];
__device__ __align__(16) float g_x4[TOKENS*DMODEL];
__device__ __align__(16) float g_sum[TOKENS*DMODEL];
__device__ __align__(16) float g_combine[TOKENS*NEXP];
__device__ __align__(16) float g_validf[NTASK*TOKENS];
__device__ __align__(16) float g_cnt[TOKENS];
__device__ int g_mask_dt[1];

__device__ __forceinline__ float gelu_f(float x) {
    return 0.5f * x * (1.0f + erff(x * 0.70710678118654752440f));
}

// ---------------- LayerNorm ----------------
__global__ void ln_kernel(const float* __restrict__ x, const float* __restrict__ w,
                          const float* __restrict__ b, float* __restrict__ y) {
    int row = blockIdx.x;
    const float* xr = x + (size_t)row * DMODEL;
    __shared__ float red[256];
    int tid = threadIdx.x;

    float s = 0.f;
    for (int i = tid; i < DMODEL; i += 256) s += xr[i];
    red[tid] = s; __syncthreads();
    for (int o = 128; o > 0; o >>= 1) { if (tid < o) red[tid] += red[tid + o]; __syncthreads(); }
    float mean = red[0] * (1.0f / DMODEL);
    __syncthreads();

    float v = 0.f;
    for (int i = tid; i < DMODEL; i += 256) { float d = xr[i] - mean; v += d * d; }
    red[tid] = v; __syncthreads();
    for (int o = 128; o > 0; o >>= 1) { if (tid < o) red[tid] += red[tid + o]; __syncthreads(); }
    float rstd = rsqrtf(red[0] * (1.0f / DMODEL) + 1e-5f);

    float* yr = y + (size_t)row * DMODEL;
    for (int i = tid; i < DMODEL; i += 256)
        yr[i] = (xr[i] - mean) * rstd * w[i] + b[i];
}

// ---------------- SGEMM 128x128x8, fused epilogue ----------------
// C[M,N] = epi(A[M,K] @ B[K,N]); requires N%128==0, K%8==0 (M ragged allowed).
__global__ __launch_bounds__(256) void sgemm_kernel(
    const float* __restrict__ A, const float* __restrict__ B, float* __restrict__ C,
    int M, int N, int K,
    const float* __restrict__ bias, const float* __restrict__ residual,
    const float* __restrict__ rowscale, int rs_stride, int flags)
{
    __shared__ float As[8][128];
    __shared__ float Bs[8][128];
    int tid = threadIdx.x;
    int row0 = blockIdx.y * 128, col0 = blockIdx.x * 128;
    int tr = tid / 16, tc = tid % 16;

    float acc[8][8];
#pragma unroll
    for (int i = 0; i < 8; i++)
#pragma unroll
        for (int j = 0; j < 8; j++) acc[i][j] = 0.f;

    int aRow = tid >> 1;          // 0..127
    int aCol = (tid & 1) * 4;     // 0 or 4
    int bRow = tid >> 5;          // 0..7
    int bCol = (tid & 31) * 4;    // 0..124

    for (int k0 = 0; k0 < K; k0 += 8) {
        float4 av;
        int gr = row0 + aRow;
        if (gr < M) av = *reinterpret_cast<const float4*>(&A[(size_t)gr * K + k0 + aCol]);
        else av = make_float4(0.f, 0.f, 0.f, 0.f);
        As[aCol + 0][aRow] = av.x; As[aCol + 1][aRow] = av.y;
        As[aCol + 2][aRow] = av.z; As[aCol + 3][aRow] = av.w;

        float4 bv = *reinterpret_cast<const float4*>(&B[(size_t)(k0 + bRow) * N + col0 + bCol]);
        *reinterpret_cast<float4*>(&Bs[bRow][bCol]) = bv;
        __syncthreads();

#pragma unroll
        for (int k = 0; k < 8; k++) {
            float ra[8], rb[8];
#pragma unroll
            for (int i = 0; i < 8; i++) ra[i] = As[k][tr * 8 + i];
#pragma unroll
            for (int j = 0; j < 8; j++) rb[j] = Bs[k][tc * 8 + j];
#pragma unroll
            for (int i = 0; i < 8; i++)
#pragma unroll
                for (int j = 0; j < 8; j++) acc[i][j] += ra[i] * rb[j];
        }
        __syncthreads();
    }

    bool do_gelu = (flags & FLAG_GELU) != 0;
    bool do_acc  = (flags & FLAG_ACC)  != 0;
#pragma unroll
    for (int i = 0; i < 8; i++) {
        int r = row0 + tr * 8 + i;
        if (r >= M) continue;
        float rs = 1.f;
        if (rowscale) rs = rowscale[(size_t)r * rs_stride];
#pragma unroll
        for (int j = 0; j < 8; j++) {
            int c = col0 + tc * 8 + j;
            float v = acc[i][j];
            if (bias) v += bias[c];
            if (do_gelu) v = gelu_f(v);
            v *= rs;
            if (residual) v += residual[(size_t)r * N + c];
            size_t idx = (size_t)r * N + c;
            if (do_acc) C[idx] += v; else C[idx] = v;
        }
    }
}

// ---------------- Attention: scores S[bh,n,m] = (q.k)/8 ----------------
__global__ void attn_scores_kernel(const float* __restrict__ qkv, float* __restrict__ S) {
    int bh = blockIdx.z;
    int b = bh / NHEAD, h = bh % NHEAD;
    int n0 = blockIdx.y * 16, m0 = blockIdx.x * 16;
    __shared__ float Qs[16][65];
    __shared__ float Ks[16][65];
    int tid = threadIdx.y * 16 + threadIdx.x;
    int idx = tid * 4;
    int r = idx >> 6, c = idx & 63;

    if (n0 + r < NSEQ) {
        const float* src = qkv + ((size_t)(b * NSEQ + n0 + r) * 3 + 0) * DMODEL + h * HD + c;
        float4 v = *reinterpret_cast<const float4*>(src);
        Qs[r][c] = v.x; Qs[r][c + 1] = v.y; Qs[r][c + 2] = v.z; Qs[r][c + 3] = v.w;
    } else {
        Qs[r][c] = Qs[r][c + 1] = Qs[r][c + 2] = Qs[r][c + 3] = 0.f;
    }
    if (m0 + r < NSEQ) {
        const float* src = qkv + ((size_t)(b * NSEQ + m0 + r) * 3 + 1) * DMODEL + h * HD + c;
        float4 v = *reinterpret_cast<const float4*>(src);
        Ks[r][c] = v.x; Ks[r][c + 1] = v.y; Ks[r][c + 2] = v.z; Ks[r][c + 3] = v.w;
    } else {
        Ks[r][c] = Ks[r][c + 1] = Ks[r][c + 2] = Ks[r][c + 3] = 0.f;
    }
    __syncthreads();

    int n = n0 + threadIdx.y, m = m0 + threadIdx.x;
    if (n < NSEQ && m < NSEQ) {
        float acc = 0.f;
#pragma unroll
        for (int d = 0; d < HD; d++) acc += Qs[threadIdx.y][d] * Ks[threadIdx.x][d];
        S[((size_t)bh * NSEQ + n) * NSEQ + m] = acc * 0.125f;
    }
}

// ---------------- row softmax over 197 ----------------
__global__ void softmax_kernel(float* __restrict__ S) {
    int row = blockIdx.x;
    float* p = S + (size_t)row * NSEQ;
    __shared__ float red[128];
    int tid = threadIdx.x;

    float m = -1e30f;
    for (int i = tid; i < NSEQ; i += 128) m = fmaxf(m, p[i]);
    red[tid] = m; __syncthreads();
    for (int o = 64; o > 0; o >>= 1) { if (tid < o) red[tid] = fmaxf(red[tid], red[tid + o]); __syncthreads(); }
    m = red[0]; __syncthreads();

    float s = 0.f;
    for (int i = tid; i < NSEQ; i += 128) { float e = __expf(p[i] - m); p[i] = e; s += e; }
    red[tid] = s; __syncthreads();
    for (int o = 64; o > 0; o >>= 1) { if (tid < o) red[tid] += red[tid + o]; __syncthreads(); }
    float inv = 1.0f / red[0];
    for (int i = tid; i < NSEQ; i += 128) p[i] *= inv;
}

// ---------------- out[b,n,h,d] = sum_m P[bh,n,m] * V[b,m,h,d] ----------------
__global__ void attn_av_kernel(const float* __restrict__ S, const float* __restrict__ qkv,
                               float* __restrict__ out) {
    int bh = blockIdx.x;
    int b = bh / NHEAD, h = bh % NHEAD;
    int n = blockIdx.y * 4 + threadIdx.y;
    int d = threadIdx.x;
    if (n >= NSEQ) return;
    const float* Sr = S + ((size_t)bh * NSEQ + n) * NSEQ;
    float acc = 0.f;
    for (int m = 0; m < NSEQ; m++)
        acc += Sr[m] * qkv[((size_t)(b * NSEQ + m) * 3 + 2) * DMODEL + h * HD + d];
    out[(size_t)(b * NSEQ + n) * DMODEL + h * HD + d] = acc;
}

// ---------------- MoE gate: softmax over 8, top-4 scatter ----------------
__global__ void gate_kernel(const float* __restrict__ x, const float* __restrict__ gw,
                            float* __restrict__ combine) {
    int token = blockIdx.x;
    int warp = threadIdx.x / 32, lane = threadIdx.x % 32;
    const float* xr = x + (size_t)token * DMODEL;
    float acc = 0.f;
    for (int d = lane; d < DMODEL; d += 32) acc += xr[d] * gw[(size_t)d * NEXP + warp];
#pragma unroll
    for (int o = 16; o > 0; o >>= 1) acc += __shfl_down_sync(0xffffffffu, acc, o);
    __shared__ float lg[NEXP];
    if (lane == 0) lg[warp] = acc;
    __syncthreads();
    if (threadIdx.x == 0) {
        float mx = lg[0];
        for (int e = 1; e < NEXP; e++) mx = fmaxf(mx, lg[e]);
        float p[NEXP]; float se = 0.f;
        for (int e = 0; e < NEXP; e++) { p[e] = __expf(lg[e] - mx); se += p[e]; }
        float inv = 1.0f / se;
        for (int e = 0; e < NEXP; e++) p[e] *= inv;
        float outv[NEXP]; bool used[NEXP];
        for (int e = 0; e < NEXP; e++) { outv[e] = 0.f; used[e] = false; }
        for (int k = 0; k < 4; k++) {
            int best = -1; float bv = -1.f;
            for (int e = 0; e < NEXP; e++)
                if (!used[e] && p[e] > bv) { bv = p[e]; best = e; }
            used[best] = true; outv[best] = bv;
        }
        for (int e = 0; e < NEXP; e++) combine[(size_t)token * NEXP + e] = outv[e];
    }
}

// ---------------- elementwise helpers ----------------
__global__ void zero_kernel(float* __restrict__ p, int n) {
    int i = blockIdx.x * blockDim.x + threadIdx.x;
    if (i < n) p[i] = 0.f;
}
__global__ void add_kernel(const float* __restrict__ a, const float* __restrict__ b,
                           float* __restrict__ o, int n) {
    int i = blockIdx.x * blockDim.x + threadIdx.x;
    if (i < n) o[i] = a[i] + b[i];
}

// ---------------- mask dtype sniffing (bool may arrive as u8/i32/f32) ----------------
__global__ void detect_mask_kernel(const unsigned int* __restrict__ w, int nwords) {
    __shared__ int flags[2]; // [not_int32, not_f32]
    if (threadIdx.x < 2) flags[threadIdx.x] = 0;
    __syncthreads();
    int ni = 0, nf = 0;
    for (int i = threadIdx.x; i < nwords; i += blockDim.x) {
        unsigned v = w[i];
        if (v > 1u) ni = 1;
        if (v != 0u && v != 0x3F800000u) nf = 1;
    }
    if (ni) flags[0] = 1;
    if (nf) flags[1] = 1;
    __syncthreads();
    if (threadIdx.x == 0)
        g_mask_dt[0] = (!flags[0]) ? 0 : ((!flags[1]) ? 1 : 2);
}

__device__ __forceinline__ float read_mask(const void* p, size_t idx, int dt) {
    if (dt == 0) return ((const int*)p)[idx] ? 1.f : 0.f;
    if (dt == 1) return ((const float*)p)[idx] != 0.f ? 1.f : 0.f;
    return ((const unsigned char*)p)[idx] ? 1.f : 0.f;
}

__global__ void valid_kernel(const void* __restrict__ sm, const void* __restrict__ am,
                             float* __restrict__ validf, float* __restrict__ cnt) {
    int t = blockIdx.x * blockDim.x + threadIdx.x;
    if (t >= TOKENS) return;
    int dt = g_mask_dt[0];
    float a = read_mask(am, t, dt);
    float c = 0.f;
    for (int k = 0; k < NTASK; k++) {
        float v = read_mask(sm, (size_t)k * TOKENS + t, dt) * a;
        validf[(size_t)k * TOKENS + t] = v;
        c += v;
    }
    cnt[t] = c;
}

__global__ void final_kernel(const float* __restrict__ summed, const float* __restrict__ cnt,
                             float* __restrict__ out) {
    int i = blockIdx.x * blockDim.x + threadIdx.x;
    if (i >= TOKENS * DMODEL) return;
    out[i] = summed[i] / (cnt[i / DMODEL] + 1e-6f);
}

// ---------------- host orchestration ----------------
static float* sym_f(const void* symbol) {
    void* p = nullptr;
    cudaGetSymbolAddress(&p, symbol);
    return (float*)p;
}

static void launch_gemm(const float* A, const float* B, float* C, int M, int N, int K,
                        const float* bias, const float* residual,
                        const float* rowscale, int rs_stride, int flags) {
    dim3 grid(N / 128, (M + 127) / 128);
    sgemm_kernel<<<grid, 256>>>(A, B, C, M, N, K, bias, residual, rowscale, rs_stride, flags);
}

extern "C" void kernel_launch(void* const* d_in, const int* in_sizes, int n_in,
                              void* d_out, int out_size) {
    const float* x       = (const float*)d_in[0];
    const float* ln1a_w  = (const float*)d_in[1];
    const float* ln1a_b  = (const float*)d_in[2];
    const float* qkv_wa  = (const float*)d_in[3];
    const float* qkv_ba  = (const float*)d_in[4];
    const float* proj_wa = (const float*)d_in[5];
    const float* proj_ba = (const float*)d_in[6];
    const float* ln2a_w  = (const float*)d_in[7];
    const float* ln2a_b  = (const float*)d_in[8];
    const float* fc1_w   = (const float*)d_in[9];
    const float* fc1_b   = (const float*)d_in[10];
    const float* fc2_w   = (const float*)d_in[11];
    const float* fc2_b   = (const float*)d_in[12];
    const float* ln1b_w  = (const float*)d_in[13];
    const float* ln1b_b  = (const float*)d_in[14];
    const float* qkv_wb  = (const float*)d_in[15];
    const float* qkv_bb  = (const float*)d_in[16];
    const float* proj_wb = (const float*)d_in[17];
    const float* proj_bb = (const float*)d_in[18];
    const float* ln2b_w  = (const float*)d_in[19];
    const float* ln2b_b  = (const float*)d_in[20];
    const float* gate_w  = (const float*)d_in[21];
    const float* w1      = (const float*)d_in[22];
    const float* b1      = (const float*)d_in[23];
    const float* w2      = (const float*)d_in[24];
    const float* b2      = (const float*)d_in[25];
    const float* head_w  = (const float*)d_in[26];
    const float* head_b  = (const float*)d_in[27];
    const void*  smask   = d_in[28];
    const void*  amask   = d_in[29];
    float* out = (float*)d_out;

    float* ln_buf  = sym_f(g_ln);
    float* qkv     = sym_f(g_qkv);
    float* S       = sym_f(g_S);
    float* attn    = sym_f(g_attn);
    float* hbuf    = sym_f(g_h);
    float* x1      = sym_f(g_x1);
    float* x2      = sym_f(g_x2);
    float* x3      = sym_f(g_x3);
    float* ybuf    = sym_f(g_y);
    float* x4      = sym_f(g_x4);
    float* sumbuf  = sym_f(g_sum);
    float* combine = sym_f(g_combine);
    float* validf  = sym_f(g_validf);
    float* cnt     = sym_f(g_cnt);

    dim3 sc_grid(13, 13, BH), sc_blk(16, 16);
    dim3 av_grid(BH, (NSEQ + 3) / 4), av_blk(64, 4);

    // ===== dense block A =====
    ln_kernel<<<TOKENS, 256>>>(x, ln1a_w, ln1a_b, ln_buf);
    launch_gemm(ln_buf, qkv_wa, qkv, TOKENS, 3 * DMODEL, DMODEL, qkv_ba, nullptr, nullptr, 0, 0);
    attn_scores_kernel<<<sc_grid, sc_blk>>>(qkv, S);
    softmax_kernel<<<BH * NSEQ, 128>>>(S);
    attn_av_kernel<<<av_grid, av_blk>>>(S, qkv, attn);
    launch_gemm(attn, proj_wa, x1, TOKENS, DMODEL, DMODEL, proj_ba, x, nullptr, 0, 0);

    ln_kernel<<<TOKENS, 256>>>(x1, ln2a_w, ln2a_b, ln_buf);
    launch_gemm(ln_buf, fc1_w, hbuf, TOKENS, HID, DMODEL, fc1_b, nullptr, nullptr, 0, FLAG_GELU);
    launch_gemm(hbuf, fc2_w, x2, TOKENS, DMODEL, HID, fc2_b, x1, nullptr, 0, 0);

    // ===== MoE block B: attention =====
    ln_kernel<<<TOKENS, 256>>>(x2, ln1b_w, ln1b_b, ln_buf);
    launch_gemm(ln_buf, qkv_wb, qkv, TOKENS, 3 * DMODEL, DMODEL, qkv_bb, nullptr, nullptr, 0, 0);
    attn_scores_kernel<<<sc_grid, sc_blk>>>(qkv, S);
    softmax_kernel<<<BH * NSEQ, 128>>>(S);
    attn_av_kernel<<<av_grid, av_blk>>>(S, qkv, attn);
    launch_gemm(attn, proj_wb, x3, TOKENS, DMODEL, DMODEL, proj_bb, x2, nullptr, 0, 0);

    // ===== MoE FFN =====
    ln_kernel<<<TOKENS, 256>>>(x3, ln2b_w, ln2b_b, ln_buf);
    gate_kernel<<<TOKENS, 256>>>(ln_buf, gate_w, combine);
    zero_kernel<<<(TOKENS * DMODEL + 255) / 256, 256>>>(ybuf, TOKENS * DMODEL);
    for (int e = 0; e < NEXP; e++) {
        launch_gemm(ln_buf, w1 + (size_t)e * DMODEL * HID, hbuf, TOKENS, HID, DMODEL,
                    b1 + (size_t)e * HID, nullptr, nullptr, 0, FLAG_GELU);
        launch_gemm(hbuf, w2 + (size_t)e * HID * DMODEL, ybuf, TOKENS, DMODEL, HID,
                    b2 + (size_t)e * DMODEL, nullptr, combine + e, NEXP, FLAG_ACC);
    }
    add_kernel<<<(TOKENS * DMODEL + 255) / 256, 256>>>(x3, ybuf, x4, TOKENS * DMODEL);

    // ===== task heads + masked aggregation =====
    detect_mask_kernel<<<1, 256>>>((const unsigned int*)smask, (NTASK * TOKENS) / 4);
    valid_kernel<<<(TOKENS + 255) / 256, 256>>>(smask, amask, validf, cnt);
    zero_kernel<<<(TOKENS * DMODEL + 255) / 256, 256>>>(sumbuf, TOKENS * DMODEL);
    for (int t = 0; t < NTASK; t++) {
        launch_gemm(x4, head_w + (size_t)t * DMODEL * DMODEL, sumbuf, TOKENS, DMODEL, DMODEL,
                    head_b + (size_t)t * DMODEL, nullptr, validf + (size_t)t * TOKENS, 1, FLAG_ACC);
    }
    final_kernel<<<(TOKENS * DMODEL + 255) / 256, 256>>>(sumbuf, cnt, out);
}

// round 9
// speedup vs baseline: 1.2122x; 1.2122x over previous
#include <cuda_runtime.h>
#include <math.h>

#define TOKENS 1576
#define DMODEL 768
#define HID 3072
#define NHEAD 12
#define HD 64
#define NSEQ 197
#define BATCH 8
#define NEXP 8
#define NTASK 8
#define BH (BATCH*NHEAD)

#define FLAG_GELU    1
#define FLAG_ACC     2
#define FLAG_GATHER  4
#define FLAG_SCATTER 8

typedef unsigned long long u64;

// ---------------- scratch (device globals; no runtime allocation) ----------------
__device__ __align__(16) float g_ln[TOKENS*DMODEL];
__device__ __align__(16) float g_qkv[TOKENS*3*DMODEL];
__device__ __align__(16) float g_S[BH*NSEQ*NSEQ];
__device__ __align__(16) float g_attn[TOKENS*DMODEL];
__device__ __align__(16) float g_h[TOKENS*HID];
__device__ __align__(16) float g_x1[TOKENS*DMODEL];
__device__ __align__(16) float g_x2[TOKENS*DMODEL];
__device__ __align__(16) float g_x3[TOKENS*DMODEL];
__device__ __align__(16) float g_y[TOKENS*DMODEL];
__device__ __align__(16) float g_x4[TOKENS*DMODEL];
__device__ __align__(16) float g_sum[TOKENS*DMODEL];
__device__ __align__(16) float g_combine[TOKENS*NEXP];
__device__ __align__(16) float g_validf[NTASK*TOKENS];
__device__ __align__(16) float g_cnt[TOKENS];
__device__ int g_mask_dt[1];
__device__ int g_ecount[NEXP];
__device__ int g_eidx[NEXP][TOKENS];

__device__ __forceinline__ float gelu_f(float x) {
    return 0.5f * x * (1.0f + erff(x * 0.70710678118654752440f));
}

// ---------------- packed f32x2 helpers (sm_100+ PTX; ptxas never auto-fuses) ----
__device__ __forceinline__ u64 pack2(float lo, float hi) {
    u64 r; asm("mov.b64 %0, {%1, %2};" : "=l"(r) : "f"(lo), "f"(hi)); return r;
}
__device__ __forceinline__ u64 ffma2(u64 a, u64 b, u64 c) {
    u64 d; asm("fma.rn.f32x2 %0, %1, %2, %3;" : "=l"(d) : "l"(a), "l"(b), "l"(c));
    return d;
}
__device__ __forceinline__ float2 unpack2(u64 v) {
    float lo, hi; asm("mov.b64 {%0, %1}, %2;" : "=f"(lo), "=f"(hi) : "l"(v));
    return make_float2(lo, hi);
}

// ---------------- LayerNorm ----------------
__global__ void ln_kernel(const float* __restrict__ x, const float* __restrict__ w,
                          const float* __restrict__ b, float* __restrict__ y) {
    int row = blockIdx.x;
    const float* xr = x + (size_t)row * DMODEL;
    __shared__ float red[256];
    int tid = threadIdx.x;

    float s = 0.f;
    for (int i = tid; i < DMODEL; i += 256) s += xr[i];
    red[tid] = s; __syncthreads();
    for (int o = 128; o > 0; o >>= 1) { if (tid < o) red[tid] += red[tid + o]; __syncthreads(); }
    float mean = red[0] * (1.0f / DMODEL);
    __syncthreads();

    float v = 0.f;
    for (int i = tid; i < DMODEL; i += 256) { float d = xr[i] - mean; v += d * d; }
    red[tid] = v; __syncthreads();
    for (int o = 128; o > 0; o >>= 1) { if (tid < o) red[tid] += red[tid + o]; __syncthreads(); }
    float rstd = rsqrtf(red[0] * (1.0f / DMODEL) + 1e-5f);

    float* yr = y + (size_t)row * DMODEL;
    for (int i = tid; i < DMODEL; i += 256)
        yr[i] = (xr[i] - mean) * rstd * w[i] + b[i];
}

// ---------------- SGEMM 128x128x8, f32x2 packed FMA, fused epilogue ----------------
// C = epi(A @ B). N%128==0, K%8==0. Optional row gather (A) / scatter (C) via rowidx;
// optional dynamic M via count_ptr (graph-safe: fixed grid, early-exit).
__global__ __launch_bounds__(256) void sgemm_kernel(
    const float* __restrict__ A, const float* __restrict__ B, float* __restrict__ C,
    int M, int N, int K,
    const float* __restrict__ bias, const float* __restrict__ residual,
    const float* __restrict__ rowscale, int rs_stride, int flags,
    const int* __restrict__ rowidx, const int* __restrict__ count_ptr)
{
    if (count_ptr) M = *count_ptr;
    int row0 = blockIdx.y * 128, col0 = blockIdx.x * 128;
    if (row0 >= M) return;

    __shared__ float As[8][128];
    __shared__ float Bs[8][128];
    int tid = threadIdx.x;
    int tr = tid / 16, tc = tid % 16;

    u64 acc[8][4];
#pragma unroll
    for (int i = 0; i < 8; i++)
#pragma unroll
        for (int j = 0; j < 4; j++) acc[i][j] = 0ull;

    int aRow = tid >> 1;          // 0..127
    int aCol = (tid & 1) * 4;     // 0 or 4
    int bRow = tid >> 5;          // 0..7
    int bCol = (tid & 31) * 4;    // 0..124

    // resolve A gather once
    int gr = row0 + aRow;
    bool aval = gr < M;
    int asrc = 0;
    if (aval) asrc = (flags & FLAG_GATHER) ? rowidx[gr] : gr;

    // prologue: load tile 0
    float4 av, bv;
    if (aval) av = *reinterpret_cast<const float4*>(&A[(size_t)asrc * K + aCol]);
    else av = make_float4(0.f, 0.f, 0.f, 0.f);
    bv = *reinterpret_cast<const float4*>(&B[(size_t)bRow * N + col0 + bCol]);
    As[aCol + 0][aRow] = av.x; As[aCol + 1][aRow] = av.y;
    As[aCol + 2][aRow] = av.z; As[aCol + 3][aRow] = av.w;
    *reinterpret_cast<float4*>(&Bs[bRow][bCol]) = bv;
    __syncthreads();

    for (int k0 = 0; k0 < K; k0 += 8) {
        bool has_next = (k0 + 8) < K;
        float4 av2, bv2;
        if (has_next) {
            if (aval) av2 = *reinterpret_cast<const float4*>(&A[(size_t)asrc * K + k0 + 8 + aCol]);
            else av2 = make_float4(0.f, 0.f, 0.f, 0.f);
            bv2 = *reinterpret_cast<const float4*>(&B[(size_t)(k0 + 8 + bRow) * N + col0 + bCol]);
        }

#pragma unroll
        for (int k = 0; k < 8; k++) {
            u64 rb[4];
#pragma unroll
            for (int j = 0; j < 4; j++)
                rb[j] = *reinterpret_cast<const u64*>(&Bs[k][tc * 8 + 2 * j]);
#pragma unroll
            for (int i = 0; i < 8; i++) {
                float a = As[k][tr * 8 + i];
                u64 a2 = pack2(a, a);
#pragma unroll
                for (int j = 0; j < 4; j++)
                    acc[i][j] = ffma2(a2, rb[j], acc[i][j]);
            }
        }

        if (has_next) {
            __syncthreads();
            As[aCol + 0][aRow] = av2.x; As[aCol + 1][aRow] = av2.y;
            As[aCol + 2][aRow] = av2.z; As[aCol + 3][aRow] = av2.w;
            *reinterpret_cast<float4*>(&Bs[bRow][bCol]) = bv2;
            __syncthreads();
        }
    }

    bool do_gelu = (flags & FLAG_GELU) != 0;
    bool do_acc  = (flags & FLAG_ACC)  != 0;
#pragma unroll
    for (int i = 0; i < 8; i++) {
        int r = row0 + tr * 8 + i;
        if (r >= M) continue;
        int crow = (flags & FLAG_SCATTER) ? rowidx[r] : r;
        float rs = 1.f;
        if (rowscale) rs = rowscale[(size_t)crow * rs_stride];
#pragma unroll
        for (int jp = 0; jp < 4; jp++) {
            float2 v2 = unpack2(acc[i][jp]);
            float vv0 = v2.x, vv1 = v2.y;
#pragma unroll
            for (int s = 0; s < 2; s++) {
                int c = col0 + tc * 8 + jp * 2 + s;
                float v = (s == 0) ? vv0 : vv1;
                if (bias) v += bias[c];
                if (do_gelu) v = gelu_f(v);
                v *= rs;
                if (residual) v += residual[(size_t)crow * N + c];
                size_t idx = (size_t)crow * N + c;
                if (do_acc) C[idx] += v; else C[idx] = v;
            }
        }
    }
}

// ---------------- Attention: scores S[bh,n,m] = (q.k)/8 ----------------
__global__ void attn_scores_kernel(const float* __restrict__ qkv, float* __restrict__ S) {
    int bh = blockIdx.z;
    int b = bh / NHEAD, h = bh % NHEAD;
    int n0 = blockIdx.y * 16, m0 = blockIdx.x * 16;
    __shared__ float Qs[16][65];
    __shared__ float Ks[16][65];
    int tid = threadIdx.y * 16 + threadIdx.x;
    int idx = tid * 4;
    int r = idx >> 6, c = idx & 63;

    if (n0 + r < NSEQ) {
        const float* src = qkv + ((size_t)(b * NSEQ + n0 + r) * 3 + 0) * DMODEL + h * HD + c;
        float4 v = *reinterpret_cast<const float4*>(src);
        Qs[r][c] = v.x; Qs[r][c + 1] = v.y; Qs[r][c + 2] = v.z; Qs[r][c + 3] = v.w;
    } else {
        Qs[r][c] = Qs[r][c + 1] = Qs[r][c + 2] = Qs[r][c + 3] = 0.f;
    }
    if (m0 + r < NSEQ) {
        const float* src = qkv + ((size_t)(b * NSEQ + m0 + r) * 3 + 1) * DMODEL + h * HD + c;
        float4 v = *reinterpret_cast<const float4*>(src);
        Ks[r][c] = v.x; Ks[r][c + 1] = v.y; Ks[r][c + 2] = v.z; Ks[r][c + 3] = v.w;
    } else {
        Ks[r][c] = Ks[r][c + 1] = Ks[r][c + 2] = Ks[r][c + 3] = 0.f;
    }
    __syncthreads();

    int n = n0 + threadIdx.y, m = m0 + threadIdx.x;
    if (n < NSEQ && m < NSEQ) {
        float acc = 0.f;
#pragma unroll
        for (int d = 0; d < HD; d++) acc += Qs[threadIdx.y][d] * Ks[threadIdx.x][d];
        S[((size_t)bh * NSEQ + n) * NSEQ + m] = acc * 0.125f;
    }
}

// ---------------- row softmax over 197 ----------------
__global__ void softmax_kernel(float* __restrict__ S) {
    int row = blockIdx.x;
    float* p = S + (size_t)row * NSEQ;
    __shared__ float red[128];
    int tid = threadIdx.x;

    float m = -1e30f;
    for (int i = tid; i < NSEQ; i += 128) m = fmaxf(m, p[i]);
    red[tid] = m; __syncthreads();
    for (int o = 64; o > 0; o >>= 1) { if (tid < o) red[tid] = fmaxf(red[tid], red[tid + o]); __syncthreads(); }
    m = red[0]; __syncthreads();

    float s = 0.f;
    for (int i = tid; i < NSEQ; i += 128) { float e = __expf(p[i] - m); p[i] = e; s += e; }
    red[tid] = s; __syncthreads();
    for (int o = 64; o > 0; o >>= 1) { if (tid < o) red[tid] += red[tid + o]; __syncthreads(); }
    float inv = 1.0f / red[0];
    for (int i = tid; i < NSEQ; i += 128) p[i] *= inv;
}

// ---------------- out[b,n,h,d] = sum_m P[bh,n,m] * V[b,m,h,d] ----------------
__global__ void attn_av_kernel(const float* __restrict__ S, const float* __restrict__ qkv,
                               float* __restrict__ out) {
    int bh = blockIdx.x;
    int b = bh / NHEAD, h = bh % NHEAD;
    int n = blockIdx.y * 4 + threadIdx.y;
    int d = threadIdx.x;
    if (n >= NSEQ) return;
    const float* Sr = S + ((size_t)bh * NSEQ + n) * NSEQ;
    float acc = 0.f;
    for (int m = 0; m < NSEQ; m++)
        acc += Sr[m] * qkv[((size_t)(b * NSEQ + m) * 3 + 2) * DMODEL + h * HD + d];
    out[(size_t)(b * NSEQ + n) * DMODEL + h * HD + d] = acc;
}

// ---------------- MoE gate: softmax over 8, top-4 scatter ----------------
__global__ void gate_kernel(const float* __restrict__ x, const float* __restrict__ gw,
                            float* __restrict__ combine) {
    int token = blockIdx.x;
    int warp = threadIdx.x / 32, lane = threadIdx.x % 32;
    const float* xr = x + (size_t)token * DMODEL;
    float acc = 0.f;
    for (int d = lane; d < DMODEL; d += 32) acc += xr[d] * gw[(size_t)d * NEXP + warp];
#pragma unroll
    for (int o = 16; o > 0; o >>= 1) acc += __shfl_down_sync(0xffffffffu, acc, o);
    __shared__ float lg[NEXP];
    if (lane == 0) lg[warp] = acc;
    __syncthreads();
    if (threadIdx.x == 0) {
        float mx = lg[0];
        for (int e = 1; e < NEXP; e++) mx = fmaxf(mx, lg[e]);
        float p[NEXP]; float se = 0.f;
        for (int e = 0; e < NEXP; e++) { p[e] = __expf(lg[e] - mx); se += p[e]; }
        float inv = 1.0f / se;
        for (int e = 0; e < NEXP; e++) p[e] *= inv;
        float outv[NEXP]; bool used[NEXP];
        for (int e = 0; e < NEXP; e++) { outv[e] = 0.f; used[e] = false; }
        for (int k = 0; k < 4; k++) {
            int best = -1; float bv = -1.f;
            for (int e = 0; e < NEXP; e++)
                if (!used[e] && p[e] > bv) { bv = p[e]; best = e; }
            used[best] = true; outv[best] = bv;
        }
        for (int e = 0; e < NEXP; e++) combine[(size_t)token * NEXP + e] = outv[e];
    }
}

// ---------------- per-expert token lists (top-4 routing) ----------------
__global__ void zero_counts_kernel(int* __restrict__ ecount) {
    if (threadIdx.x < NEXP) ecount[threadIdx.x] = 0;
}
__global__ void build_lists_kernel(const float* __restrict__ combine,
                                   int* __restrict__ ecount, int* __restrict__ eidx) {
    int t = blockIdx.x * blockDim.x + threadIdx.x;
    if (t >= TOKENS) return;
#pragma unroll
    for (int e = 0; e < NEXP; e++) {
        if (combine[(size_t)t * NEXP + e] > 0.f) {  // softmax probs: top-4 strictly > 0
            int pos = atomicAdd(&ecount[e], 1);
            eidx[(size_t)e * TOKENS + pos] = t;
        }
    }
}

// ---------------- elementwise helpers ----------------
__global__ void zero_kernel(float* __restrict__ p, int n) {
    int i = blockIdx.x * blockDim.x + threadIdx.x;
    if (i < n) p[i] = 0.f;
}
__global__ void add_kernel(const float* __restrict__ a, const float* __restrict__ b,
                           float* __restrict__ o, int n) {
    int i = blockIdx.x * blockDim.x + threadIdx.x;
    if (i < n) o[i] = a[i] + b[i];
}

// ---------------- mask dtype sniffing (bool may arrive as u8/i32/f32) ----------------
__global__ void detect_mask_kernel(const unsigned int* __restrict__ w, int nwords) {
    __shared__ int flags[2];
    if (threadIdx.x < 2) flags[threadIdx.x] = 0;
    __syncthreads();
    int ni = 0, nf = 0;
    for (int i = threadIdx.x; i < nwords; i += blockDim.x) {
        unsigned v = w[i];
        if (v > 1u) ni = 1;
        if (v != 0u && v != 0x3F800000u) nf = 1;
    }
    if (ni) flags[0] = 1;
    if (nf) flags[1] = 1;
    __syncthreads();
    if (threadIdx.x == 0)
        g_mask_dt[0] = (!flags[0]) ? 0 : ((!flags[1]) ? 1 : 2);
}

__device__ __forceinline__ float read_mask(const void* p, size_t idx, int dt) {
    if (dt == 0) return ((const int*)p)[idx] ? 1.f : 0.f;
    if (dt == 1) return ((const float*)p)[idx] != 0.f ? 1.f : 0.f;
    return ((const unsigned char*)p)[idx] ? 1.f : 0.f;
}

__global__ void valid_kernel(const void* __restrict__ sm, const void* __restrict__ am,
                             float* __restrict__ validf, float* __restrict__ cnt) {
    int t = blockIdx.x * blockDim.x + threadIdx.x;
    if (t >= TOKENS) return;
    int dt = g_mask_dt[0];
    float a = read_mask(am, t, dt);
    float c = 0.f;
    for (int k = 0; k < NTASK; k++) {
        float v = read_mask(sm, (size_t)k * TOKENS + t, dt) * a;
        validf[(size_t)k * TOKENS + t] = v;
        c += v;
    }
    cnt[t] = c;
}

__global__ void final_kernel(const float* __restrict__ summed, const float* __restrict__ cnt,
                             float* __restrict__ out) {
    int i = blockIdx.x * blockDim.x + threadIdx.x;
    if (i >= TOKENS * DMODEL) return;
    out[i] = summed[i] / (cnt[i / DMODEL] + 1e-6f);
}

// ---------------- host orchestration ----------------
static float* sym_f(const void* symbol) {
    void* p = nullptr;
    cudaGetSymbolAddress(&p, symbol);
    return (float*)p;
}
static int* sym_i(const void* symbol) {
    void* p = nullptr;
    cudaGetSymbolAddress(&p, symbol);
    return (int*)p;
}

static void launch_gemm(const float* A, const float* B, float* C, int M, int N, int K,
                        const float* bias, const float* residual,
                        const float* rowscale, int rs_stride, int flags,
                        const int* rowidx = nullptr, const int* count_ptr = nullptr) {
    dim3 grid(N / 128, (M + 127) / 128);
    sgemm_kernel<<<grid, 256>>>(A, B, C, M, N, K, bias, residual, rowscale, rs_stride,
                                flags, rowidx, count_ptr);
}

extern "C" void kernel_launch(void* const* d_in, const int* in_sizes, int n_in,
                              void* d_out, int out_size) {
    const float* x       = (const float*)d_in[0];
    const float* ln1a_w  = (const float*)d_in[1];
    const float* ln1a_b  = (const float*)d_in[2];
    const float* qkv_wa  = (const float*)d_in[3];
    const float* qkv_ba  = (const float*)d_in[4];
    const float* proj_wa = (const float*)d_in[5];
    const float* proj_ba = (const float*)d_in[6];
    const float* ln2a_w  = (const float*)d_in[7];
    const float* ln2a_b  = (const float*)d_in[8];
    const float* fc1_w   = (const float*)d_in[9];
    const float* fc1_b   = (const float*)d_in[10];
    const float* fc2_w   = (const float*)d_in[11];
    const float* fc2_b   = (const float*)d_in[12];
    const float* ln1b_w  = (const float*)d_in[13];
    const float* ln1b_b  = (const float*)d_in[14];
    const float* qkv_wb  = (const float*)d_in[15];
    const float* qkv_bb  = (const float*)d_in[16];
    const float* proj_wb = (const float*)d_in[17];
    const float* proj_bb = (const float*)d_in[18];
    const float* ln2b_w  = (const float*)d_in[19];
    const float* ln2b_b  = (const float*)d_in[20];
    const float* gate_w  = (const float*)d_in[21];
    const float* w1      = (const float*)d_in[22];
    const float* b1      = (const float*)d_in[23];
    const float* w2      = (const float*)d_in[24];
    const float* b2      = (const float*)d_in[25];
    const float* head_w  = (const float*)d_in[26];
    const float* head_b  = (const float*)d_in[27];
    const void*  smask   = d_in[28];
    const void*  amask   = d_in[29];
    float* out = (float*)d_out;

    float* ln_buf  = sym_f(g_ln);
    float* qkv     = sym_f(g_qkv);
    float* S       = sym_f(g_S);
    float* attn    = sym_f(g_attn);
    float* hbuf    = sym_f(g_h);
    float* x1      = sym_f(g_x1);
    float* x2      = sym_f(g_x2);
    float* x3      = sym_f(g_x3);
    float* ybuf    = sym_f(g_y);
    float* x4      = sym_f(g_x4);
    float* sumbuf  = sym_f(g_sum);
    float* combine = sym_f(g_combine);
    float* validf  = sym_f(g_validf);
    float* cnt     = sym_f(g_cnt);
    int*   ecount  = sym_i(g_ecount);
    int*   eidx    = sym_i(g_eidx);

    dim3 sc_grid(13, 13, BH), sc_blk(16, 16);
    dim3 av_grid(BH, (NSEQ + 3) / 4), av_blk(64, 4);

    // ===== dense block A =====
    ln_kernel<<<TOKENS, 256>>>(x, ln1a_w, ln1a_b, ln_buf);
    launch_gemm(ln_buf, qkv_wa, qkv, TOKENS, 3 * DMODEL, DMODEL, qkv_ba, nullptr, nullptr, 0, 0);
    attn_scores_kernel<<<sc_grid, sc_blk>>>(qkv, S);
    softmax_kernel<<<BH * NSEQ, 128>>>(S);
    attn_av_kernel<<<av_grid, av_blk>>>(S, qkv, attn);
    launch_gemm(attn, proj_wa, x1, TOKENS, DMODEL, DMODEL, proj_ba, x, nullptr, 0, 0);

    ln_kernel<<<TOKENS, 256>>>(x1, ln2a_w, ln2a_b, ln_buf);
    launch_gemm(ln_buf, fc1_w, hbuf, TOKENS, HID, DMODEL, fc1_b, nullptr, nullptr, 0, FLAG_GELU);
    launch_gemm(hbuf, fc2_w, x2, TOKENS, DMODEL, HID, fc2_b, x1, nullptr, 0, 0);

    // ===== MoE block B: attention =====
    ln_kernel<<<TOKENS, 256>>>(x2, ln1b_w, ln1b_b, ln_buf);
    launch_gemm(ln_buf, qkv_wb, qkv, TOKENS, 3 * DMODEL, DMODEL, qkv_bb, nullptr, nullptr, 0, 0);
    attn_scores_kernel<<<sc_grid, sc_blk>>>(qkv, S);
    softmax_kernel<<<BH * NSEQ, 128>>>(S);
    attn_av_kernel<<<av_grid, av_blk>>>(S, qkv, attn);
    launch_gemm(attn, proj_wb, x3, TOKENS, DMODEL, DMODEL, proj_bb, x2, nullptr, 0, 0);

    // ===== MoE FFN: top-4 gathered experts =====
    ln_kernel<<<TOKENS, 256>>>(x3, ln2b_w, ln2b_b, ln_buf);
    gate_kernel<<<TOKENS, 256>>>(ln_buf, gate_w, combine);
    zero_counts_kernel<<<1, 32>>>(ecount);
    build_lists_kernel<<<(TOKENS + 255) / 256, 256>>>(combine, ecount, eidx);
    zero_kernel<<<(TOKENS * DMODEL + 255) / 256, 256>>>(ybuf, TOKENS * DMODEL);
    for (int e = 0; e < NEXP; e++) {
        const int* idx_e = eidx + (size_t)e * TOKENS;
        const int* cnt_e = ecount + e;
        // fc1: gather selected tokens, compact output, GELU
        launch_gemm(ln_buf, w1 + (size_t)e * DMODEL * HID, hbuf, TOKENS, HID, DMODEL,
                    b1 + (size_t)e * HID, nullptr, nullptr, 0,
                    FLAG_GELU | FLAG_GATHER, idx_e, cnt_e);
        // fc2: compact input, scatter-accumulate scaled by combine weight
        launch_gemm(hbuf, w2 + (size_t)e * HID * DMODEL, ybuf, TOKENS, DMODEL, HID,
                    b2 + (size_t)e * DMODEL, nullptr, combine + e, NEXP,
                    FLAG_ACC | FLAG_SCATTER, idx_e, cnt_e);
    }
    add_kernel<<<(TOKENS * DMODEL + 255) / 256, 256>>>(x3, ybuf, x4, TOKENS * DMODEL);

    // ===== task heads + masked aggregation =====
    detect_mask_kernel<<<1, 256>>>((const unsigned int*)smask, (NTASK * TOKENS) / 4);
    valid_kernel<<<(TOKENS + 255) / 256, 256>>>(smask, amask, validf, cnt);
    zero_kernel<<<(TOKENS * DMODEL + 255) / 256, 256>>>(sumbuf, TOKENS * DMODEL);
    for (int t = 0; t < NTASK; t++) {
        launch_gemm(x4, head_w + (size_t)t * DMODEL * DMODEL, sumbuf, TOKENS, DMODEL, DMODEL,
                    head_b + (size_t)t * DMODEL, nullptr, validf + (size_t)t * TOKENS, 1, FLAG_ACC);
    }
    final_kernel<<<(TOKENS * DMODEL + 255) / 256, 256>>>(sumbuf, cnt, out);
}

// round 11
// speedup vs baseline: 2.3692x; 1.9545x over previous
#include <cuda_runtime.h>
#include <cuda_bf16.h>
#include <math.h>
#include <stdint.h>

#define TOKENS 1576
#define DMODEL 768
#define HID 3072
#define NHEAD 12
#define HD 64
#define NSEQ 197
#define BATCH 8
#define NEXP 8
#define NTASK 8
#define BH (BATCH*NHEAD)

#define FLAG_GELU    1
#define FLAG_ACC     2
#define FLAG_GATHER  4
#define FLAG_SCATTER 8

// ---------------- scratch (device globals; no runtime allocation) ----------------
__device__ __align__(16) float g_ln[TOKENS*DMODEL];
__device__ __align__(16) float g_qkv[TOKENS*3*DMODEL];
__device__ __align__(16) float g_S[BH*NSEQ*NSEQ];
__device__ __align__(16) float g_attn[TOKENS*DMODEL];
__device__ __align__(16) float g_h[TOKENS*HID];
__device__ __align__(16) float g_x1[TOKENS*DMODEL];
__device__ __align__(16) float g_x2[TOKENS*DMODEL];
__device__ __align__(16) float g_x3[TOKENS*DMODEL];
__device__ __align__(16) float g_y[TOKENS*DMODEL];
__device__ __align__(16) float g_x4[TOKENS*DMODEL];
__device__ __align__(16) float g_sum[TOKENS*DMODEL];
__device__ __align__(16) float g_combine[TOKENS*NEXP];
__device__ __align__(16) float g_validf[NTASK*TOKENS];
__device__ __align__(16) float g_cnt[TOKENS];
__device__ int g_mask_dt[1];
__device__ int g_ecount[NEXP];
__device__ int g_eidx[NEXP][TOKENS];

__device__ __forceinline__ float gelu_f(float x) {
    return 0.5f * x * (1.0f + erff(x * 0.70710678118654752440f));
}

// split fp32 -> (hi, lo) bf16 pair, pack two k-consecutive values into one b32
__device__ __forceinline__ void split_pack(float v0, float v1, uint32_t& hi, uint32_t& lo) {
    __nv_bfloat16 h0 = __float2bfloat16_rn(v0);
    __nv_bfloat16 h1 = __float2bfloat16_rn(v1);
    float r0 = v0 - __bfloat162float(h0);
    float r1 = v1 - __bfloat162float(h1);
    __nv_bfloat16 l0 = __float2bfloat16_rn(r0);
    __nv_bfloat16 l1 = __float2bfloat16_rn(r1);
    hi = ((uint32_t)__bfloat16_as_ushort(h1) << 16) | (uint32_t)__bfloat16_as_ushort(h0);
    lo = ((uint32_t)__bfloat16_as_ushort(l1) << 16) | (uint32_t)__bfloat16_as_ushort(l0);
}

__device__ __forceinline__ void mma_bf16(float& c0, float& c1, float& c2, float& c3,
                                         uint32_t a0, uint32_t a1, uint32_t a2, uint32_t a3,
                                         uint32_t b0, uint32_t b1) {
    asm volatile(
        "mma.sync.aligned.m16n8k16.row.col.f32.bf16.bf16.f32 "
        "{%0,%1,%2,%3}, {%4,%5,%6,%7}, {%8,%9}, {%0,%1,%2,%3};"
        : "+f"(c0), "+f"(c1), "+f"(c2), "+f"(c3)
        : "r"(a0), "r"(a1), "r"(a2), "r"(a3), "r"(b0), "r"(b1));
}

// ---------------- LayerNorm ----------------
__global__ void ln_kernel(const float* __restrict__ x, const float* __restrict__ w,
                          const float* __restrict__ b, float* __restrict__ y) {
    int row = blockIdx.x;
    const float* xr = x + (size_t)row * DMODEL;
    __shared__ float red[256];
    int tid = threadIdx.x;

    float s = 0.f;
    for (int i = tid; i < DMODEL; i += 256) s += xr[i];
    red[tid] = s; __syncthreads();
    for (int o = 128; o > 0; o >>= 1) { if (tid < o) red[tid] += red[tid + o]; __syncthreads(); }
    float mean = red[0] * (1.0f / DMODEL);
    __syncthreads();

    float v = 0.f;
    for (int i = tid; i < DMODEL; i += 256) { float d = xr[i] - mean; v += d * d; }
    red[tid] = v; __syncthreads();
    for (int o = 128; o > 0; o >>= 1) { if (tid < o) red[tid] += red[tid + o]; __syncthreads(); }
    float rstd = rsqrtf(red[0] * (1.0f / DMODEL) + 1e-5f);

    float* yr = y + (size_t)row * DMODEL;
    for (int i = tid; i < DMODEL; i += 256)
        yr[i] = (xr[i] - mean) * rstd * w[i] + b[i];
}

// ---------- split-bf16 tensor-core GEMM 128x128x32, 3-term, fused epilogue ----------
// C = epi(A @ B), fp32 in/out. N%128==0, K%32==0. gather(A)/scatter(C); dynamic M.
// SMEM holds k-pair-packed bf16x2 planes: [k2][m] / [k2][n], stride 136 (==8 mod 32,
// -> fragment LDS bank = 8*tg + grp, conflict-free).
#define BK 32
#define BK2 16
#define ASTR 136
#define BSTR 136

__global__ __launch_bounds__(256) void sgemm_kernel(
    const float* __restrict__ A, const float* __restrict__ B, float* __restrict__ C,
    int M, int N, int K,
    const float* __restrict__ bias, const float* __restrict__ residual,
    const float* __restrict__ rowscale, int rs_stride, int flags,
    const int* __restrict__ rowidx, const int* __restrict__ count_ptr)
{
    if (count_ptr) M = *count_ptr;
    int row0 = blockIdx.y * 128, col0 = blockIdx.x * 128;
    if (row0 >= M) return;

    __shared__ uint32_t AsH[BK2 * ASTR];
    __shared__ uint32_t AsL[BK2 * ASTR];
    __shared__ uint32_t BsH[BK2 * BSTR];
    __shared__ uint32_t BsL[BK2 * BSTR];

    int tid = threadIdx.x;
    int lane = tid & 31;
    int warp = tid >> 5;
    int grp = lane >> 2;       // 0..7
    int tg  = lane & 3;        // 0..3
    int warp_m = (warp & 1) * 64;
    int warp_n = (warp >> 1) * 32;

    // A: row = tid%128, k-quad base = (tid>>7)*4 -> float4 at k = q*8 + aK
    int aRow = tid & 127;
    int aK   = (tid >> 7) * 4;      // 0 or 4
    // B: k-pair kp = q*8 + (tid>>5), cols lane*4..+3 (two rows 2kp, 2kp+1)
    int bkp  = tid >> 5;            // 0..7
    int bCol = lane * 4;

    int gr = row0 + aRow;
    bool aval = gr < M;
    int asrc = 0;
    if (aval) asrc = (flags & FLAG_GATHER) ? rowidx[gr] : gr;

    float acc[4][4][4];
#pragma unroll
    for (int i = 0; i < 4; i++)
#pragma unroll
        for (int j = 0; j < 4; j++)
#pragma unroll
            for (int r = 0; r < 4; r++) acc[i][j][r] = 0.f;

    float4 avr[4];
    float4 b0v[2], b1v[2];

    // prologue: load k-tile 0
#pragma unroll
    for (int q = 0; q < 4; q++) {
        int kk = q * 8 + aK;
        if (aval) avr[q] = *reinterpret_cast<const float4*>(&A[(size_t)asrc * K + kk]);
        else avr[q] = make_float4(0.f, 0.f, 0.f, 0.f);
    }
#pragma unroll
    for (int q = 0; q < 2; q++) {
        int kp = q * 8 + bkp;
        b0v[q] = *reinterpret_cast<const float4*>(&B[(size_t)(2 * kp) * N + col0 + bCol]);
        b1v[q] = *reinterpret_cast<const float4*>(&B[(size_t)(2 * kp + 1) * N + col0 + bCol]);
    }

    // store tile 0
#pragma unroll
    for (int q = 0; q < 4; q++) {
        int k2 = q * 4 + (aK >> 1);
        uint32_t ph0, pl0, ph1, pl1;
        split_pack(avr[q].x, avr[q].y, ph0, pl0);
        split_pack(avr[q].z, avr[q].w, ph1, pl1);
        AsH[k2 * ASTR + aRow] = ph0; AsH[(k2 + 1) * ASTR + aRow] = ph1;
        AsL[k2 * ASTR + aRow] = pl0; AsL[(k2 + 1) * ASTR + aRow] = pl1;
    }
#pragma unroll
    for (int q = 0; q < 2; q++) {
        int kp = q * 8 + bkp;
        uint32_t ph[4], pl[4];
        split_pack(b0v[q].x, b1v[q].x, ph[0], pl[0]);
        split_pack(b0v[q].y, b1v[q].y, ph[1], pl[1]);
        split_pack(b0v[q].z, b1v[q].z, ph[2], pl[2]);
        split_pack(b0v[q].w, b1v[q].w, ph[3], pl[3]);
        *reinterpret_cast<uint4*>(&BsH[kp * BSTR + bCol]) = make_uint4(ph[0], ph[1], ph[2], ph[3]);
        *reinterpret_cast<uint4*>(&BsL[kp * BSTR + bCol]) = make_uint4(pl[0], pl[1], pl[2], pl[3]);
    }
    __syncthreads();

    for (int k0 = 0; k0 < K; k0 += BK) {
        bool has_next = (k0 + BK) < K;
        if (has_next) {
#pragma unroll
            for (int q = 0; q < 4; q++) {
                int kk = k0 + BK + q * 8 + aK;
                if (aval) avr[q] = *reinterpret_cast<const float4*>(&A[(size_t)asrc * K + kk]);
                else avr[q] = make_float4(0.f, 0.f, 0.f, 0.f);
            }
#pragma unroll
            for (int q = 0; q < 2; q++) {
                int kp = q * 8 + bkp;
                b0v[q] = *reinterpret_cast<const float4*>(&B[(size_t)(k0 + BK + 2 * kp) * N + col0 + bCol]);
                b1v[q] = *reinterpret_cast<const float4*>(&B[(size_t)(k0 + BK + 2 * kp + 1) * N + col0 + bCol]);
            }
        }

        // compute: 2 k16 steps, 3-term split mma
#pragma unroll
        for (int kk = 0; kk < 2; kk++) {
            int kb2 = kk * 8;
            uint32_t bh[4][2], bl[4][2];
#pragma unroll
            for (int j = 0; j < 4; j++) {
                int n = warp_n + j * 8 + grp;
                bh[j][0] = BsH[(kb2 + tg) * BSTR + n];
                bh[j][1] = BsH[(kb2 + tg + 4) * BSTR + n];
                bl[j][0] = BsL[(kb2 + tg) * BSTR + n];
                bl[j][1] = BsL[(kb2 + tg + 4) * BSTR + n];
            }
#pragma unroll
            for (int i = 0; i < 4; i++) {
                int m = warp_m + i * 16 + grp;
                uint32_t ah0 = AsH[(kb2 + tg) * ASTR + m];
                uint32_t ah1 = AsH[(kb2 + tg) * ASTR + m + 8];
                uint32_t ah2 = AsH[(kb2 + tg + 4) * ASTR + m];
                uint32_t ah3 = AsH[(kb2 + tg + 4) * ASTR + m + 8];
                uint32_t al0 = AsL[(kb2 + tg) * ASTR + m];
                uint32_t al1 = AsL[(kb2 + tg) * ASTR + m + 8];
                uint32_t al2 = AsL[(kb2 + tg + 4) * ASTR + m];
                uint32_t al3 = AsL[(kb2 + tg + 4) * ASTR + m + 8];
#pragma unroll
                for (int j = 0; j < 4; j++) {
                    mma_bf16(acc[i][j][0], acc[i][j][1], acc[i][j][2], acc[i][j][3],
                             ah0, ah1, ah2, ah3, bh[j][0], bh[j][1]);
                    mma_bf16(acc[i][j][0], acc[i][j][1], acc[i][j][2], acc[i][j][3],
                             ah0, ah1, ah2, ah3, bl[j][0], bl[j][1]);
                    mma_bf16(acc[i][j][0], acc[i][j][1], acc[i][j][2], acc[i][j][3],
                             al0, al1, al2, al3, bh[j][0], bh[j][1]);
                }
            }
        }

        if (has_next) {
            __syncthreads();
#pragma unroll
            for (int q = 0; q < 4; q++) {
                int k2 = q * 4 + (aK >> 1);
                uint32_t ph0, pl0, ph1, pl1;
                split_pack(avr[q].x, avr[q].y, ph0, pl0);
                split_pack(avr[q].z, avr[q].w, ph1, pl1);
                AsH[k2 * ASTR + aRow] = ph0; AsH[(k2 + 1) * ASTR + aRow] = ph1;
                AsL[k2 * ASTR + aRow] = pl0; AsL[(k2 + 1) * ASTR + aRow] = pl1;
            }
#pragma unroll
            for (int q = 0; q < 2; q++) {
                int kp = q * 8 + bkp;
                uint32_t ph[4], pl[4];
                split_pack(b0v[q].x, b1v[q].x, ph[0], pl[0]);
                split_pack(b0v[q].y, b1v[q].y, ph[1], pl[1]);
                split_pack(b0v[q].z, b1v[q].z, ph[2], pl[2]);
                split_pack(b0v[q].w, b1v[q].w, ph[3], pl[3]);
                *reinterpret_cast<uint4*>(&BsH[kp * BSTR + bCol]) = make_uint4(ph[0], ph[1], ph[2], ph[3]);
                *reinterpret_cast<uint4*>(&BsL[kp * BSTR + bCol]) = make_uint4(pl[0], pl[1], pl[2], pl[3]);
            }
            __syncthreads();
        }
    }

    // epilogue: m16n8 C fragment: (c0,c1)->row grp cols 2tg,2tg+1; (c2,c3)->row grp+8
    bool do_gelu = (flags & FLAG_GELU) != 0;
    bool do_acc  = (flags & FLAG_ACC)  != 0;
#pragma unroll
    for (int i = 0; i < 4; i++) {
#pragma unroll
        for (int half = 0; half < 2; half++) {
            int r = row0 + warp_m + i * 16 + grp + half * 8;
            if (r >= M) continue;
            int crow = (flags & FLAG_SCATTER) ? rowidx[r] : r;
            float rs = 1.f;
            if (rowscale) rs = rowscale[(size_t)crow * rs_stride];
#pragma unroll
            for (int j = 0; j < 4; j++) {
#pragma unroll
                for (int s = 0; s < 2; s++) {
                    int c = col0 + warp_n + j * 8 + tg * 2 + s;
                    float v = acc[i][j][half * 2 + s];
                    if (bias) v += bias[c];
                    if (do_gelu) v = gelu_f(v);
                    v *= rs;
                    if (residual) v += residual[(size_t)crow * N + c];
                    size_t idx = (size_t)crow * N + c;
                    if (do_acc) C[idx] += v; else C[idx] = v;
                }
            }
        }
    }
}

// ---------------- Attention: scores S[bh,n,m] = (q.k)/8 ----------------
__global__ void attn_scores_kernel(const float* __restrict__ qkv, float* __restrict__ S) {
    int bh = blockIdx.z;
    int b = bh / NHEAD, h = bh % NHEAD;
    int n0 = blockIdx.y * 16, m0 = blockIdx.x * 16;
    __shared__ float Qs[16][65];
    __shared__ float Ks[16][65];
    int tid = threadIdx.y * 16 + threadIdx.x;
    int idx = tid * 4;
    int r = idx >> 6, c = idx & 63;

    if (n0 + r < NSEQ) {
        const float* src = qkv + ((size_t)(b * NSEQ + n0 + r) * 3 + 0) * DMODEL + h * HD + c;
        float4 v = *reinterpret_cast<const float4*>(src);
        Qs[r][c] = v.x; Qs[r][c + 1] = v.y; Qs[r][c + 2] = v.z; Qs[r][c + 3] = v.w;
    } else {
        Qs[r][c] = Qs[r][c + 1] = Qs[r][c + 2] = Qs[r][c + 3] = 0.f;
    }
    if (m0 + r < NSEQ) {
        const float* src = qkv + ((size_t)(b * NSEQ + m0 + r) * 3 + 1) * DMODEL + h * HD + c;
        float4 v = *reinterpret_cast<const float4*>(src);
        Ks[r][c] = v.x; Ks[r][c + 1] = v.y; Ks[r][c + 2] = v.z; Ks[r][c + 3] = v.w;
    } else {
        Ks[r][c] = Ks[r][c + 1] = Ks[r][c + 2] = Ks[r][c + 3] = 0.f;
    }
    __syncthreads();

    int n = n0 + threadIdx.y, m = m0 + threadIdx.x;
    if (n < NSEQ && m < NSEQ) {
        float acc = 0.f;
#pragma unroll
        for (int d = 0; d < HD; d++) acc += Qs[threadIdx.y][d] * Ks[threadIdx.x][d];
        S[((size_t)bh * NSEQ + n) * NSEQ + m] = acc * 0.125f;
    }
}

// ---------------- row softmax over 197 ----------------
__global__ void softmax_kernel(float* __restrict__ S) {
    int row = blockIdx.x;
    float* p = S + (size_t)row * NSEQ;
    __shared__ float red[128];
    int tid = threadIdx.x;

    float m = -1e30f;
    for (int i = tid; i < NSEQ; i += 128) m = fmaxf(m, p[i]);
    red[tid] = m; __syncthreads();
    for (int o = 64; o > 0; o >>= 1) { if (tid < o) red[tid] = fmaxf(red[tid], red[tid + o]); __syncthreads(); }
    m = red[0]; __syncthreads();

    float s = 0.f;
    for (int i = tid; i < NSEQ; i += 128) { float e = __expf(p[i] - m); p[i] = e; s += e; }
    red[tid] = s; __syncthreads();
    for (int o = 64; o > 0; o >>= 1) { if (tid < o) red[tid] += red[tid + o]; __syncthreads(); }
    float inv = 1.0f / red[0];
    for (int i = tid; i < NSEQ; i += 128) p[i] *= inv;
}

// ---------------- out[b,n,h,d] = sum_m P[bh,n,m] * V[b,m,h,d] ----------------
__global__ void attn_av_kernel(const float* __restrict__ S, const float* __restrict__ qkv,
                               float* __restrict__ out) {
    int bh = blockIdx.x;
    int b = bh / NHEAD, h = bh % NHEAD;
    int n = blockIdx.y * 4 + threadIdx.y;
    int d = threadIdx.x;
    if (n >= NSEQ) return;
    const float* Sr = S + ((size_t)bh * NSEQ + n) * NSEQ;
    float acc = 0.f;
    for (int m = 0; m < NSEQ; m++)
        acc += Sr[m] * qkv[((size_t)(b * NSEQ + m) * 3 + 2) * DMODEL + h * HD + d];
    out[(size_t)(b * NSEQ + n) * DMODEL + h * HD + d] = acc;
}

// ---------------- MoE gate: softmax over 8, top-4 scatter ----------------
__global__ void gate_kernel(const float* __restrict__ x, const float* __restrict__ gw,
                            float* __restrict__ combine) {
    int token = blockIdx.x;
    int warp = threadIdx.x / 32, lane = threadIdx.x % 32;
    const float* xr = x + (size_t)token * DMODEL;
    float acc = 0.f;
    for (int d = lane; d < DMODEL; d += 32) acc += xr[d] * gw[(size_t)d * NEXP + warp];
#pragma unroll
    for (int o = 16; o > 0; o >>= 1) acc += __shfl_down_sync(0xffffffffu, acc, o);
    __shared__ float lg[NEXP];
    if (lane == 0) lg[warp] = acc;
    __syncthreads();
    if (threadIdx.x == 0) {
        float mx = lg[0];
        for (int e = 1; e < NEXP; e++) mx = fmaxf(mx, lg[e]);
        float p[NEXP]; float se = 0.f;
        for (int e = 0; e < NEXP; e++) { p[e] = __expf(lg[e] - mx); se += p[e]; }
        float inv = 1.0f / se;
        for (int e = 0; e < NEXP; e++) p[e] *= inv;
        float outv[NEXP]; bool used[NEXP];
        for (int e = 0; e < NEXP; e++) { outv[e] = 0.f; used[e] = false; }
        for (int k = 0; k < 4; k++) {
            int best = -1; float bv = -1.f;
            for (int e = 0; e < NEXP; e++)
                if (!used[e] && p[e] > bv) { bv = p[e]; best = e; }
            used[best] = true; outv[best] = bv;
        }
        for (int e = 0; e < NEXP; e++) combine[(size_t)token * NEXP + e] = outv[e];
    }
}

// ---------------- per-expert token lists (top-4 routing) ----------------
__global__ void zero_counts_kernel(int* __restrict__ ecount) {
    if (threadIdx.x < NEXP) ecount[threadIdx.x] = 0;
}
__global__ void build_lists_kernel(const float* __restrict__ combine,
                                   int* __restrict__ ecount, int* __restrict__ eidx) {
    int t = blockIdx.x * blockDim.x + threadIdx.x;
    if (t >= TOKENS) return;
#pragma unroll
    for (int e = 0; e < NEXP; e++) {
        if (combine[(size_t)t * NEXP + e] > 0.f) {
            int pos = atomicAdd(&ecount[e], 1);
            eidx[(size_t)e * TOKENS + pos] = t;
        }
    }
}

// ---------------- elementwise helpers ----------------
__global__ void zero_kernel(float* __restrict__ p, int n) {
    int i = blockIdx.x * blockDim.x + threadIdx.x;
    if (i < n) p[i] = 0.f;
}
__global__ void add_kernel(const float* __restrict__ a, const float* __restrict__ b,
                           float* __restrict__ o, int n) {
    int i = blockIdx.x * blockDim.x + threadIdx.x;
    if (i < n) o[i] = a[i] + b[i];
}

// ---------------- mask dtype sniffing (bool may arrive as u8/i32/f32) ----------------
__global__ void detect_mask_kernel(const unsigned int* __restrict__ w, int nwords) {
    __shared__ int flags[2];
    if (threadIdx.x < 2) flags[threadIdx.x] = 0;
    __syncthreads();
    int ni = 0, nf = 0;
    for (int i = threadIdx.x; i < nwords; i += blockDim.x) {
        unsigned v = w[i];
        if (v > 1u) ni = 1;
        if (v != 0u && v != 0x3F800000u) nf = 1;
    }
    if (ni) flags[0] = 1;
    if (nf) flags[1] = 1;
    __syncthreads();
    if (threadIdx.x == 0)
        g_mask_dt[0] = (!flags[0]) ? 0 : ((!flags[1]) ? 1 : 2);
}

__device__ __forceinline__ float read_mask(const void* p, size_t idx, int dt) {
    if (dt == 0) return ((const int*)p)[idx] ? 1.f : 0.f;
    if (dt == 1) return ((const float*)p)[idx] != 0.f ? 1.f : 0.f;
    return ((const unsigned char*)p)[idx] ? 1.f : 0.f;
}

__global__ void valid_kernel(const void* __restrict__ sm, const void* __restrict__ am,
                             float* __restrict__ validf, float* __restrict__ cnt) {
    int t = blockIdx.x * blockDim.x + threadIdx.x;
    if (t >= TOKENS) return;
    int dt = g_mask_dt[0];
    float a = read_mask(am, t, dt);
    float c = 0.f;
    for (int k = 0; k < NTASK; k++) {
        float v = read_mask(sm, (size_t)k * TOKENS + t, dt) * a;
        validf[(size_t)k * TOKENS + t] = v;
        c += v;
    }
    cnt[t] = c;
}

__global__ void final_kernel(const float* __restrict__ summed, const float* __restrict__ cnt,
                             float* __restrict__ out) {
    int i = blockIdx.x * blockDim.x + threadIdx.x;
    if (i >= TOKENS * DMODEL) return;
    out[i] = summed[i] / (cnt[i / DMODEL] + 1e-6f);
}

// ---------------- host orchestration ----------------
static float* sym_f(const void* symbol) {
    void* p = nullptr;
    cudaGetSymbolAddress(&p, symbol);
    return (float*)p;
}
static int* sym_i(const void* symbol) {
    void* p = nullptr;
    cudaGetSymbolAddress(&p, symbol);
    return (int*)p;
}

static void launch_gemm(const float* A, const float* B, float* C, int M, int N, int K,
                        const float* bias, const float* residual,
                        const float* rowscale, int rs_stride, int flags,
                        const int* rowidx = nullptr, const int* count_ptr = nullptr) {
    dim3 grid(N / 128, (M + 127) / 128);
    sgemm_kernel<<<grid, 256>>>(A, B, C, M, N, K, bias, residual, rowscale, rs_stride,
                                flags, rowidx, count_ptr);
}

extern "C" void kernel_launch(void* const* d_in, const int* in_sizes, int n_in,
                              void* d_out, int out_size) {
    const float* x       = (const float*)d_in[0];
    const float* ln1a_w  = (const float*)d_in[1];
    const float* ln1a_b  = (const float*)d_in[2];
    const float* qkv_wa  = (const float*)d_in[3];
    const float* qkv_ba  = (const float*)d_in[4];
    const float* proj_wa = (const float*)d_in[5];
    const float* proj_ba = (const float*)d_in[6];
    const float* ln2a_w  = (const float*)d_in[7];
    const float* ln2a_b  = (const float*)d_in[8];
    const float* fc1_w   = (const float*)d_in[9];
    const float* fc1_b   = (const float*)d_in[10];
    const float* fc2_w   = (const float*)d_in[11];
    const float* fc2_b   = (const float*)d_in[12];
    const float* ln1b_w  = (const float*)d_in[13];
    const float* ln1b_b  = (const float*)d_in[14];
    const float* qkv_wb  = (const float*)d_in[15];
    const float* qkv_bb  = (const float*)d_in[16];
    const float* proj_wb = (const float*)d_in[17];
    const float* proj_bb = (const float*)d_in[18];
    const float* ln2b_w  = (const float*)d_in[19];
    const float* ln2b_b  = (const float*)d_in[20];
    const float* gate_w  = (const float*)d_in[21];
    const float* w1      = (const float*)d_in[22];
    const float* b1      = (const float*)d_in[23];
    const float* w2      = (const float*)d_in[24];
    const float* b2      = (const float*)d_in[25];
    const float* head_w  = (const float*)d_in[26];
    const float* head_b  = (const float*)d_in[27];
    const void*  smask   = d_in[28];
    const void*  amask   = d_in[29];
    float* out = (float*)d_out;

    float* ln_buf  = sym_f(g_ln);
    float* qkv     = sym_f(g_qkv);
    float* S       = sym_f(g_S);
    float* attn    = sym_f(g_attn);
    float* hbuf    = sym_f(g_h);
    float* x1      = sym_f(g_x1);
    float* x2      = sym_f(g_x2);
    float* x3      = sym_f(g_x3);
    float* ybuf    = sym_f(g_y);
    float* x4      = sym_f(g_x4);
    float* sumbuf  = sym_f(g_sum);
    float* combine = sym_f(g_combine);
    float* validf  = sym_f(g_validf);
    float* cnt     = sym_f(g_cnt);
    int*   ecount  = sym_i(g_ecount);
    int*   eidx    = sym_i(g_eidx);

    dim3 sc_grid(13, 13, BH), sc_blk(16, 16);
    dim3 av_grid(BH, (NSEQ + 3) / 4), av_blk(64, 4);

    // ===== dense block A =====
    ln_kernel<<<TOKENS, 256>>>(x, ln1a_w, ln1a_b, ln_buf);
    launch_gemm(ln_buf, qkv_wa, qkv, TOKENS, 3 * DMODEL, DMODEL, qkv_ba, nullptr, nullptr, 0, 0);
    attn_scores_kernel<<<sc_grid, sc_blk>>>(qkv, S);
    softmax_kernel<<<BH * NSEQ, 128>>>(S);
    attn_av_kernel<<<av_grid, av_blk>>>(S, qkv, attn);
    launch_gemm(attn, proj_wa, x1, TOKENS, DMODEL, DMODEL, proj_ba, x, nullptr, 0, 0);

    ln_kernel<<<TOKENS, 256>>>(x1, ln2a_w, ln2a_b, ln_buf);
    launch_gemm(ln_buf, fc1_w, hbuf, TOKENS, HID, DMODEL, fc1_b, nullptr, nullptr, 0, FLAG_GELU);
    launch_gemm(hbuf, fc2_w, x2, TOKENS, DMODEL, HID, fc2_b, x1, nullptr, 0, 0);

    // ===== MoE block B: attention =====
    ln_kernel<<<TOKENS, 256>>>(x2, ln1b_w, ln1b_b, ln_buf);
    launch_gemm(ln_buf, qkv_wb, qkv, TOKENS, 3 * DMODEL, DMODEL, qkv_bb, nullptr, nullptr, 0, 0);
    attn_scores_kernel<<<sc_grid, sc_blk>>>(qkv, S);
    softmax_kernel<<<BH * NSEQ, 128>>>(S);
    attn_av_kernel<<<av_grid, av_blk>>>(S, qkv, attn);
    launch_gemm(attn, proj_wb, x3, TOKENS, DMODEL, DMODEL, proj_bb, x2, nullptr, 0, 0);

    // ===== MoE FFN: top-4 gathered experts =====
    ln_kernel<<<TOKENS, 256>>>(x3, ln2b_w, ln2b_b, ln_buf);
    gate_kernel<<<TOKENS, 256>>>(ln_buf, gate_w, combine);
    zero_counts_kernel<<<1, 32>>>(ecount);
    build_lists_kernel<<<(TOKENS + 255) / 256, 256>>>(combine, ecount, eidx);
    zero_kernel<<<(TOKENS * DMODEL + 255) / 256, 256>>>(ybuf, TOKENS * DMODEL);
    for (int e = 0; e < NEXP; e++) {
        const int* idx_e = eidx + (size_t)e * TOKENS;
        const int* cnt_e = ecount + e;
        launch_gemm(ln_buf, w1 + (size_t)e * DMODEL * HID, hbuf, TOKENS, HID, DMODEL,
                    b1 + (size_t)e * HID, nullptr, nullptr, 0,
                    FLAG_GELU | FLAG_GATHER, idx_e, cnt_e);
        launch_gemm(hbuf, w2 + (size_t)e * HID * DMODEL, ybuf, TOKENS, DMODEL, HID,
                    b2 + (size_t)e * DMODEL, nullptr, combine + e, NEXP,
                    FLAG_ACC | FLAG_SCATTER, idx_e, cnt_e);
    }
    add_kernel<<<(TOKENS * DMODEL + 255) / 256, 256>>>(x3, ybuf, x4, TOKENS * DMODEL);

    // ===== task heads + masked aggregation =====
    detect_mask_kernel<<<1, 256>>>((const unsigned int*)smask, (NTASK * TOKENS) / 4);
    valid_kernel<<<(TOKENS + 255) / 256, 256>>>(smask, amask, validf, cnt);
    zero_kernel<<<(TOKENS * DMODEL + 255) / 256, 256>>>(sumbuf, TOKENS * DMODEL);
    for (int t = 0; t < NTASK; t++) {
        launch_gemm(x4, head_w + (size_t)t * DMODEL * DMODEL, sumbuf, TOKENS, DMODEL, DMODEL,
                    head_b + (size_t)t * DMODEL, nullptr, validf + (size_t)t * TOKENS, 1, FLAG_ACC);
    }
    final_kernel<<<(TOKENS * DMODEL + 255) / 256, 256>>>(sumbuf, cnt, out);
}

// round 13
// speedup vs baseline: 2.9517x; 1.2459x over previous
#include <cuda_runtime.h>
#include <cuda_bf16.h>
#include <math.h>
#include <stdint.h>

#define TOKENS 1576
#define DMODEL 768
#define HID 3072
#define NHEAD 12
#define HD 64
#define NSEQ 197
#define BATCH 8
#define NEXP 8
#define NTASK 8
#define BH (BATCH*NHEAD)

#define FLAG_GELU    1
#define FLAG_ACC     2
#define FLAG_GATHER  4
#define FLAG_SCATTER 8

typedef __nv_bfloat16 bf16;

// ---------------- fp32 scratch ----------------
__device__ __align__(16) float g_ln[TOKENS*DMODEL];
__device__ __align__(16) float g_qkv[TOKENS*3*DMODEL];
__device__ __align__(16) float g_S[BH*NSEQ*NSEQ];
__device__ __align__(16) float g_x1[TOKENS*DMODEL];
__device__ __align__(16) float g_x2[TOKENS*DMODEL];
__device__ __align__(16) float g_x3[TOKENS*DMODEL];
__device__ __align__(16) float g_y[TOKENS*DMODEL];
__device__ __align__(16) float g_sum[TOKENS*DMODEL];
__device__ __align__(16) float g_combine[TOKENS*NEXP];
__device__ __align__(16) float g_validf[NTASK*TOKENS];
__device__ __align__(16) float g_cnt[TOKENS];
__device__ int g_mask_dt[1];
__device__ int g_ecount[NEXP];
__device__ int g_eidx[NEXP][TOKENS];

// ---------------- bf16 hi/lo plane arenas ----------------
#define WQKV  (768*2304)
#define WPROJ (768*768)
#define WFC   (768*3072)
#define WW1   (8*768*3072)
#define WW2   (8*3072*768)
#define WHEAD (8*768*768)
#define OFF_QKVA  ((size_t)0)
#define OFF_PROJA (OFF_QKVA + WQKV)
#define OFF_FC1   (OFF_PROJA + WPROJ)
#define OFF_FC2   (OFF_FC1 + WFC)
#define OFF_QKVB  (OFF_FC2 + WFC)
#define OFF_PROJB (OFF_QKVB + WQKV)
#define OFF_W1    (OFF_PROJB + WPROJ)
#define OFF_W2    (OFF_W1 + WW1)
#define OFF_HEAD  (OFF_W2 + WW2)
#define TOTALW    (OFF_HEAD + WHEAD)

__device__ __align__(16) bf16 g_wh[TOTALW];
__device__ __align__(16) bf16 g_wl[TOTALW];
__device__ __align__(16) bf16 g_lnp_h[TOKENS*DMODEL];
__device__ __align__(16) bf16 g_lnp_l[TOKENS*DMODEL];
__device__ __align__(16) bf16 g_attnp_h[TOKENS*DMODEL];
__device__ __align__(16) bf16 g_attnp_l[TOKENS*DMODEL];
__device__ __align__(16) bf16 g_hp_h[TOKENS*HID];
__device__ __align__(16) bf16 g_hp_l[TOKENS*HID];
__device__ __align__(16) bf16 g_x4p_h[TOKENS*DMODEL];
__device__ __align__(16) bf16 g_x4p_l[TOKENS*DMODEL];

__device__ __forceinline__ float gelu_f(float x) {
    return 0.5f * x * (1.0f + erff(x * 0.70710678118654752440f));
}
__device__ __forceinline__ void split_store(float v, bf16* h, bf16* l, size_t idx) {
    bf16 hb = __float2bfloat16_rn(v);
    h[idx] = hb;
    l[idx] = __float2bfloat16_rn(v - __bfloat162float(hb));
}

__device__ __forceinline__ void mma_bf16(float& c0, float& c1, float& c2, float& c3,
                                         uint32_t a0, uint32_t a1, uint32_t a2, uint32_t a3,
                                         uint32_t b0, uint32_t b1) {
    asm volatile(
        "mma.sync.aligned.m16n8k16.row.col.f32.bf16.bf16.f32 "
        "{%0,%1,%2,%3}, {%4,%5,%6,%7}, {%8,%9}, {%0,%1,%2,%3};"
        : "+f"(c0), "+f"(c1), "+f"(c2), "+f"(c3)
        : "r"(a0), "r"(a1), "r"(a2), "r"(a3), "r"(b0), "r"(b1));
}
#define LDSM_X4(r0,r1,r2,r3,addr) \
    asm volatile("ldmatrix.sync.aligned.m8n8.x4.shared.b16 {%0,%1,%2,%3}, [%4];" \
        : "=r"(r0),"=r"(r1),"=r"(r2),"=r"(r3) : "r"(addr))
#define LDSM_X4_T(r0,r1,r2,r3,addr) \
    asm volatile("ldmatrix.sync.aligned.m8n8.x4.trans.shared.b16 {%0,%1,%2,%3}, [%4];" \
        : "=r"(r0),"=r"(r1),"=r"(r2),"=r"(r3) : "r"(addr))
__device__ __forceinline__ void cp16(uint32_t dst, const void* src, int bytes) {
    asm volatile("cp.async.cg.shared.global [%0], [%1], 16, %2;"
                 :: "r"(dst), "l"(src), "r"(bytes));
}
#define CP_COMMIT() asm volatile("cp.async.commit_group;" ::: "memory")
#define CP_WAIT1()  asm volatile("cp.async.wait_group 1;" ::: "memory")
#define CP_WAIT0()  asm volatile("cp.async.wait_group 0;" ::: "memory")

// ---------------- weight split ----------------
__global__ void split_kernel(const float4* __restrict__ src, bf16* __restrict__ h,
                             bf16* __restrict__ l, int n4) {
    int i = blockIdx.x * 256 + threadIdx.x;
    if (i >= n4) return;
    float4 v = src[i];
    float vs[4] = {v.x, v.y, v.z, v.w};
    ushort hh[4], ll[4];
#pragma unroll
    for (int k = 0; k < 4; k++) {
        bf16 hb = __float2bfloat16_rn(vs[k]);
        bf16 lb = __float2bfloat16_rn(vs[k] - __bfloat162float(hb));
        hh[k] = __bfloat16_as_ushort(hb);
        ll[k] = __bfloat16_as_ushort(lb);
    }
    uint2 ph = make_uint2(((uint32_t)hh[1] << 16) | hh[0], ((uint32_t)hh[3] << 16) | hh[2]);
    uint2 pl = make_uint2(((uint32_t)ll[1] << 16) | ll[0], ((uint32_t)ll[3] << 16) | ll[2]);
    reinterpret_cast<uint2*>(h)[i] = ph;
    reinterpret_cast<uint2*>(l)[i] = pl;
}

// ---------------- LayerNorm (fp32 out + split planes) ----------------
__global__ void ln_kernel(const float* __restrict__ x, const float* __restrict__ w,
                          const float* __restrict__ b, float* __restrict__ y,
                          bf16* __restrict__ yh, bf16* __restrict__ yl) {
    int row = blockIdx.x;
    const float* xr = x + (size_t)row * DMODEL;
    __shared__ float red[256];
    int tid = threadIdx.x;

    float s = 0.f;
    for (int i = tid; i < DMODEL; i += 256) s += xr[i];
    red[tid] = s; __syncthreads();
    for (int o = 128; o > 0; o >>= 1) { if (tid < o) red[tid] += red[tid + o]; __syncthreads(); }
    float mean = red[0] * (1.0f / DMODEL);
    __syncthreads();

    float v = 0.f;
    for (int i = tid; i < DMODEL; i += 256) { float d = xr[i] - mean; v += d * d; }
    red[tid] = v; __syncthreads();
    for (int o = 128; o > 0; o >>= 1) { if (tid < o) red[tid] += red[tid + o]; __syncthreads(); }
    float rstd = rsqrtf(red[0] * (1.0f / DMODEL) + 1e-5f);

    for (int i = tid; i < DMODEL; i += 256) {
        float val = (xr[i] - mean) * rstd * w[i] + b[i];
        y[(size_t)row * DMODEL + i] = val;
        split_store(val, yh, yl, (size_t)row * DMODEL + i);
    }
}

// ======== split-bf16 tensor GEMM: 128x128x32, cp.async 2-stage, ldmatrix ========
// C = epi(A@B). A planes [M][K] k-contig, B planes [K][N]. N%128==0, K%32==0.
#define ASTR 40
#define BSTR 136
#define APL 5120   // 128*40 elems
#define BPL 4352   // 32*136 elems
#define SMEM_BYTES (2*2*APL*2 + 2*2*BPL*2)   // 75776

__global__ __launch_bounds__(256) void gemm2_kernel(
    const bf16* __restrict__ Ah, const bf16* __restrict__ Al,
    const bf16* __restrict__ Bh, const bf16* __restrict__ Bl,
    float* __restrict__ C, bf16* __restrict__ Ch, bf16* __restrict__ Cl,
    int M, int N, int K,
    const float* __restrict__ bias, const float* __restrict__ residual,
    const float* __restrict__ rowscale, int rs_stride, int flags,
    const int* __restrict__ rowidx, const int* __restrict__ count_ptr)
{
    if (count_ptr) M = *count_ptr;
    int row0 = blockIdx.y * 128, col0 = blockIdx.x * 128;
    if (row0 >= M) return;

    extern __shared__ char smem[];
    uint32_t sbase = (uint32_t)__cvta_generic_to_shared(smem);

    int tid = threadIdx.x;
    int lane = tid & 31;
    int warp = tid >> 5;
    int grp = lane >> 2, tg = lane & 3;
    int warp_m = (warp & 1) * 64;
    int warp_n = (warp >> 1) * 32;

    // --- precompute loader slots ---
    int a_pl[4], a_r[4], a_c[4], a_src[4], a_sz[4];
#pragma unroll
    for (int s = 0; s < 4; s++) {
        int cid = tid + 256 * s;
        a_pl[s] = cid >> 9; a_r[s] = (cid >> 2) & 127; a_c[s] = cid & 3;
        int gr = row0 + a_r[s];
        bool valid = gr < M;
        a_src[s] = valid ? ((flags & FLAG_GATHER) ? rowidx[gr] : gr) : 0;
        a_sz[s] = valid ? 16 : 0;
    }
    int b_pl[4], b_r[4], b_c[4];
#pragma unroll
    for (int s = 0; s < 4; s++) {
        int cid = tid + 256 * s;
        b_pl[s] = cid >> 9; b_r[s] = (cid >> 4) & 31; b_c[s] = cid & 15;
    }

    auto load_stage = [&](int k0, int stage) {
#pragma unroll
        for (int s = 0; s < 4; s++) {
            const bf16* base = a_pl[s] ? Al : Ah;
            uint32_t dst = sbase + (uint32_t)(stage * 2 + a_pl[s]) * (APL * 2)
                         + (uint32_t)(a_r[s] * ASTR + a_c[s] * 8) * 2;
            cp16(dst, base + (size_t)a_src[s] * K + k0 + a_c[s] * 8, a_sz[s]);
        }
#pragma unroll
        for (int s = 0; s < 4; s++) {
            const bf16* base = b_pl[s] ? Bl : Bh;
            uint32_t dst = sbase + (uint32_t)(2 * 2 * APL * 2)
                         + (uint32_t)(stage * 2 + b_pl[s]) * (BPL * 2)
                         + (uint32_t)(b_r[s] * BSTR + b_c[s] * 8) * 2;
            cp16(dst, base + (size_t)(k0 + b_r[s]) * N + col0 + b_c[s] * 8, 16);
        }
    };

    float acc[4][4][4];
#pragma unroll
    for (int i = 0; i < 4; i++)
#pragma unroll
        for (int j = 0; j < 4; j++)
#pragma unroll
            for (int r = 0; r < 4; r++) acc[i][j][r] = 0.f;

    int nK = K / 32;
    load_stage(0, 0);
    CP_COMMIT();

    for (int kt = 0; kt < nK; kt++) {
        int buf = kt & 1;
        if (kt + 1 < nK) {
            load_stage((kt + 1) * 32, buf ^ 1);
            CP_COMMIT();
            CP_WAIT1();
        } else {
            CP_WAIT0();
        }
        __syncthreads();

        uint32_t aBaseH = sbase + (uint32_t)(buf * 2 + 0) * (APL * 2);
        uint32_t aBaseL = sbase + (uint32_t)(buf * 2 + 1) * (APL * 2);
        uint32_t bBaseH = sbase + (uint32_t)(2 * 2 * APL * 2) + (uint32_t)(buf * 2 + 0) * (BPL * 2);
        uint32_t bBaseL = sbase + (uint32_t)(2 * 2 * APL * 2) + (uint32_t)(buf * 2 + 1) * (BPL * 2);

#pragma unroll
        for (int kb = 0; kb < 32; kb += 16) {
            uint32_t bh[4][2], bl[4][2];
#pragma unroll
            for (int jj = 0; jj < 2; jj++) {
                int rowk = kb + (lane & 7) + ((lane >> 3) & 1) * 8;
                int coln = warp_n + jj * 16 + (lane >> 4) * 8;
                uint32_t off = (uint32_t)(rowk * BSTR + coln) * 2;
                LDSM_X4_T(bh[2*jj][0], bh[2*jj][1], bh[2*jj+1][0], bh[2*jj+1][1], bBaseH + off);
                LDSM_X4_T(bl[2*jj][0], bl[2*jj][1], bl[2*jj+1][0], bl[2*jj+1][1], bBaseL + off);
            }
#pragma unroll
            for (int i = 0; i < 4; i++) {
                int rowm = warp_m + i * 16 + (lane & 15);
                int colk = kb + (lane >> 4) * 8;
                uint32_t off = (uint32_t)(rowm * ASTR + colk) * 2;
                uint32_t ah0, ah1, ah2, ah3, al0, al1, al2, al3;
                LDSM_X4(ah0, ah1, ah2, ah3, aBaseH + off);
                LDSM_X4(al0, al1, al2, al3, aBaseL + off);
#pragma unroll
                for (int j = 0; j < 4; j++) {
                    mma_bf16(acc[i][j][0], acc[i][j][1], acc[i][j][2], acc[i][j][3],
                             ah0, ah1, ah2, ah3, bh[j][0], bh[j][1]);
                    mma_bf16(acc[i][j][0], acc[i][j][1], acc[i][j][2], acc[i][j][3],
                             ah0, ah1, ah2, ah3, bl[j][0], bl[j][1]);
                    mma_bf16(acc[i][j][0], acc[i][j][1], acc[i][j][2], acc[i][j][3],
                             al0, al1, al2, al3, bh[j][0], bh[j][1]);
                }
            }
        }
        __syncthreads();
    }

    // epilogue
    bool do_gelu = (flags & FLAG_GELU) != 0;
    bool do_acc  = (flags & FLAG_ACC)  != 0;
#pragma unroll
    for (int i = 0; i < 4; i++) {
#pragma unroll
        for (int half = 0; half < 2; half++) {
            int r = row0 + warp_m + i * 16 + grp + half * 8;
            if (r >= M) continue;
            int crow = (flags & FLAG_SCATTER) ? rowidx[r] : r;
            float rs = 1.f;
            if (rowscale) rs = rowscale[(size_t)crow * rs_stride];
#pragma unroll
            for (int j = 0; j < 4; j++) {
#pragma unroll
                for (int s = 0; s < 2; s++) {
                    int c = col0 + warp_n + j * 8 + tg * 2 + s;
                    float v = acc[i][j][half * 2 + s];
                    if (bias) v += bias[c];
                    if (do_gelu) v = gelu_f(v);
                    v *= rs;
                    if (residual) v += residual[(size_t)crow * N + c];
                    size_t idx = (size_t)crow * N + c;
                    if (Ch) split_store(v, Ch, Cl, idx);
                    if (C) { if (do_acc) C[idx] += v; else C[idx] = v; }
                }
            }
        }
    }
}

// ---------------- Attention: scores S[bh,n,m] = (q.k)/8 ----------------
__global__ void attn_scores_kernel(const float* __restrict__ qkv, float* __restrict__ S) {
    int bh = blockIdx.z;
    int b = bh / NHEAD, h = bh % NHEAD;
    int n0 = blockIdx.y * 16, m0 = blockIdx.x * 16;
    __shared__ float Qs[16][65];
    __shared__ float Ks[16][65];
    int tid = threadIdx.y * 16 + threadIdx.x;
    int idx = tid * 4;
    int r = idx >> 6, c = idx & 63;

    if (n0 + r < NSEQ) {
        const float* src = qkv + ((size_t)(b * NSEQ + n0 + r) * 3 + 0) * DMODEL + h * HD + c;
        float4 v = *reinterpret_cast<const float4*>(src);
        Qs[r][c] = v.x; Qs[r][c + 1] = v.y; Qs[r][c + 2] = v.z; Qs[r][c + 3] = v.w;
    } else {
        Qs[r][c] = Qs[r][c + 1] = Qs[r][c + 2] = Qs[r][c + 3] = 0.f;
    }
    if (m0 + r < NSEQ) {
        const float* src = qkv + ((size_t)(b * NSEQ + m0 + r) * 3 + 1) * DMODEL + h * HD + c;
        float4 v = *reinterpret_cast<const float4*>(src);
        Ks[r][c] = v.x; Ks[r][c + 1] = v.y; Ks[r][c + 2] = v.z; Ks[r][c + 3] = v.w;
    } else {
        Ks[r][c] = Ks[r][c + 1] = Ks[r][c + 2] = Ks[r][c + 3] = 0.f;
    }
    __syncthreads();

    int n = n0 + threadIdx.y, m = m0 + threadIdx.x;
    if (n < NSEQ && m < NSEQ) {
        float acc = 0.f;
#pragma unroll
        for (int d = 0; d < HD; d++) acc += Qs[threadIdx.y][d] * Ks[threadIdx.x][d];
        S[((size_t)bh * NSEQ + n) * NSEQ + m] = acc * 0.125f;
    }
}

// ---------------- row softmax over 197 ----------------
__global__ void softmax_kernel(float* __restrict__ S) {
    int row = blockIdx.x;
    float* p = S + (size_t)row * NSEQ;
    __shared__ float red[128];
    int tid = threadIdx.x;

    float m = -1e30f;
    for (int i = tid; i < NSEQ; i += 128) m = fmaxf(m, p[i]);
    red[tid] = m; __syncthreads();
    for (int o = 64; o > 0; o >>= 1) { if (tid < o) red[tid] = fmaxf(red[tid], red[tid + o]); __syncthreads(); }
    m = red[0]; __syncthreads();

    float s = 0.f;
    for (int i = tid; i < NSEQ; i += 128) { float e = __expf(p[i] - m); p[i] = e; s += e; }
    red[tid] = s; __syncthreads();
    for (int o = 64; o > 0; o >>= 1) { if (tid < o) red[tid] += red[tid + o]; __syncthreads(); }
    float inv = 1.0f / red[0];
    for (int i = tid; i < NSEQ; i += 128) p[i] *= inv;
}

// ------------- out planes = split(sum_m P[bh,n,m] * V[b,m,h,d]) -------------
__global__ void attn_av_kernel(const float* __restrict__ S, const float* __restrict__ qkv,
                               bf16* __restrict__ oh, bf16* __restrict__ ol) {
    int bh = blockIdx.x;
    int b = bh / NHEAD, h = bh % NHEAD;
    int n = blockIdx.y * 4 + threadIdx.y;
    int d = threadIdx.x;
    if (n >= NSEQ) return;
    const float* Sr = S + ((size_t)bh * NSEQ + n) * NSEQ;
    float acc = 0.f;
    for (int m = 0; m < NSEQ; m++)
        acc += Sr[m] * qkv[((size_t)(b * NSEQ + m) * 3 + 2) * DMODEL + h * HD + d];
    split_store(acc, oh, ol, (size_t)(b * NSEQ + n) * DMODEL + h * HD + d);
}

// ---------------- MoE gate ----------------
__global__ void gate_kernel(const float* __restrict__ x, const float* __restrict__ gw,
                            float* __restrict__ combine) {
    int token = blockIdx.x;
    int warp = threadIdx.x / 32, lane = threadIdx.x % 32;
    const float* xr = x + (size_t)token * DMODEL;
    float acc = 0.f;
    for (int d = lane; d < DMODEL; d += 32) acc += xr[d] * gw[(size_t)d * NEXP + warp];
#pragma unroll
    for (int o = 16; o > 0; o >>= 1) acc += __shfl_down_sync(0xffffffffu, acc, o);
    __shared__ float lg[NEXP];
    if (lane == 0) lg[warp] = acc;
    __syncthreads();
    if (threadIdx.x == 0) {
        float mx = lg[0];
        for (int e = 1; e < NEXP; e++) mx = fmaxf(mx, lg[e]);
        float p[NEXP]; float se = 0.f;
        for (int e = 0; e < NEXP; e++) { p[e] = __expf(lg[e] - mx); se += p[e]; }
        float inv = 1.0f / se;
        for (int e = 0; e < NEXP; e++) p[e] *= inv;
        float outv[NEXP]; bool used[NEXP];
        for (int e = 0; e < NEXP; e++) { outv[e] = 0.f; used[e] = false; }
        for (int k = 0; k < 4; k++) {
            int best = -1; float bv = -1.f;
            for (int e = 0; e < NEXP; e++)
                if (!used[e] && p[e] > bv) { bv = p[e]; best = e; }
            used[best] = true; outv[best] = bv;
        }
        for (int e = 0; e < NEXP; e++) combine[(size_t)token * NEXP + e] = outv[e];
    }
}

__global__ void zero_counts_kernel(int* __restrict__ ecount) {
    if (threadIdx.x < NEXP) ecount[threadIdx.x] = 0;
}
__global__ void build_lists_kernel(const float* __restrict__ combine,
                                   int* __restrict__ ecount, int* __restrict__ eidx) {
    int t = blockIdx.x * blockDim.x + threadIdx.x;
    if (t >= TOKENS) return;
#pragma unroll
    for (int e = 0; e < NEXP; e++) {
        if (combine[(size_t)t * NEXP + e] > 0.f) {
            int pos = atomicAdd(&ecount[e], 1);
            eidx[(size_t)e * TOKENS + pos] = t;
        }
    }
}

__global__ void zero_kernel(float* __restrict__ p, int n) {
    int i = blockIdx.x * blockDim.x + threadIdx.x;
    if (i < n) p[i] = 0.f;
}
__global__ void add_split_kernel(const float* __restrict__ a, const float* __restrict__ b,
                                 bf16* __restrict__ oh, bf16* __restrict__ ol, int n) {
    int i = blockIdx.x * blockDim.x + threadIdx.x;
    if (i < n) split_store(a[i] + b[i], oh, ol, i);
}

// ---------------- mask dtype sniffing ----------------
__global__ void detect_mask_kernel(const unsigned int* __restrict__ w, int nwords) {
    __shared__ int flags[2];
    if (threadIdx.x < 2) flags[threadIdx.x] = 0;
    __syncthreads();
    int ni = 0, nf = 0;
    for (int i = threadIdx.x; i < nwords; i += blockDim.x) {
        unsigned v = w[i];
        if (v > 1u) ni = 1;
        if (v != 0u && v != 0x3F800000u) nf = 1;
    }
    if (ni) flags[0] = 1;
    if (nf) flags[1] = 1;
    __syncthreads();
    if (threadIdx.x == 0)
        g_mask_dt[0] = (!flags[0]) ? 0 : ((!flags[1]) ? 1 : 2);
}
__device__ __forceinline__ float read_mask(const void* p, size_t idx, int dt) {
    if (dt == 0) return ((const int*)p)[idx] ? 1.f : 0.f;
    if (dt == 1) return ((const float*)p)[idx] != 0.f ? 1.f : 0.f;
    return ((const unsigned char*)p)[idx] ? 1.f : 0.f;
}
__global__ void valid_kernel(const void* __restrict__ sm, const void* __restrict__ am,
                             float* __restrict__ validf, float* __restrict__ cnt) {
    int t = blockIdx.x * blockDim.x + threadIdx.x;
    if (t >= TOKENS) return;
    int dt = g_mask_dt[0];
    float a = read_mask(am, t, dt);
    float c = 0.f;
    for (int k = 0; k < NTASK; k++) {
        float v = read_mask(sm, (size_t)k * TOKENS + t, dt) * a;
        validf[(size_t)k * TOKENS + t] = v;
        c += v;
    }
    cnt[t] = c;
}
__global__ void final_kernel(const float* __restrict__ summed, const float* __restrict__ cnt,
                             float* __restrict__ out) {
    int i = blockIdx.x * blockDim.x + threadIdx.x;
    if (i >= TOKENS * DMODEL) return;
    out[i] = summed[i] / (cnt[i / DMODEL] + 1e-6f);
}

// ---------------- host orchestration ----------------
static float* sym_f(const void* s) { void* p = nullptr; cudaGetSymbolAddress(&p, s); return (float*)p; }
static int*   sym_i(const void* s) { void* p = nullptr; cudaGetSymbolAddress(&p, s); return (int*)p; }
static bf16*  sym_b(const void* s) { void* p = nullptr; cudaGetSymbolAddress(&p, s); return (bf16*)p; }

static void launch_split(const float* src, bf16* h, bf16* l, size_t n) {
    int n4 = (int)(n / 4);
    split_kernel<<<(n4 + 255) / 256, 256>>>((const float4*)src, h, l, n4);
}

static void launch_gemm(const bf16* Ah, const bf16* Al, const bf16* Bh, const bf16* Bl,
                        float* C, bf16* Ch, bf16* Cl, int M, int N, int K,
                        const float* bias, const float* residual,
                        const float* rowscale, int rs_stride, int flags,
                        const int* rowidx = nullptr, const int* count_ptr = nullptr) {
    dim3 grid(N / 128, (M + 127) / 128);
    gemm2_kernel<<<grid, 256, SMEM_BYTES>>>(Ah, Al, Bh, Bl, C, Ch, Cl, M, N, K,
                                            bias, residual, rowscale, rs_stride,
                                            flags, rowidx, count_ptr);
}

extern "C" void kernel_launch(void* const* d_in, const int* in_sizes, int n_in,
                              void* d_out, int out_size) {
    const float* x       = (const float*)d_in[0];
    const float* ln1a_w  = (const float*)d_in[1];
    const float* ln1a_b  = (const float*)d_in[2];
    const float* qkv_wa  = (const float*)d_in[3];
    const float* qkv_ba  = (const float*)d_in[4];
    const float* proj_wa = (const float*)d_in[5];
    const float* proj_ba = (const float*)d_in[6];
    const float* ln2a_w  = (const float*)d_in[7];
    const float* ln2a_b  = (const float*)d_in[8];
    const float* fc1_w   = (const float*)d_in[9];
    const float* fc1_b   = (const float*)d_in[10];
    const float* fc2_w   = (const float*)d_in[11];
    const float* fc2_b   = (const float*)d_in[12];
    const float* ln1b_w  = (const float*)d_in[13];
    const float* ln1b_b  = (const float*)d_in[14];
    const float* qkv_wb  = (const float*)d_in[15];
    const float* qkv_bb  = (const float*)d_in[16];
    const float* proj_wb = (const float*)d_in[17];
    const float* proj_bb = (const float*)d_in[18];
    const float* ln2b_w  = (const float*)d_in[19];
    const float* ln2b_b  = (const float*)d_in[20];
    const float* gate_w  = (const float*)d_in[21];
    const float* w1      = (const float*)d_in[22];
    const float* b1      = (const float*)d_in[23];
    const float* w2      = (const float*)d_in[24];
    const float* b2      = (const float*)d_in[25];
    const float* head_w  = (const float*)d_in[26];
    const float* head_b  = (const float*)d_in[27];
    const void*  smask   = d_in[28];
    const void*  amask   = d_in[29];
    float* out = (float*)d_out;

    cudaFuncSetAttribute(gemm2_kernel, cudaFuncAttributeMaxDynamicSharedMemorySize, SMEM_BYTES);

    float* ln_buf  = sym_f(g_ln);
    float* qkv     = sym_f(g_qkv);
    float* S       = sym_f(g_S);
    float* x1      = sym_f(g_x1);
    float* x2      = sym_f(g_x2);
    float* x3      = sym_f(g_x3);
    float* ybuf    = sym_f(g_y);
    float* sumbuf  = sym_f(g_sum);
    float* combine = sym_f(g_combine);
    float* validf  = sym_f(g_validf);
    float* cnt     = sym_f(g_cnt);
    int*   ecount  = sym_i(g_ecount);
    int*   eidx    = sym_i(g_eidx);

    bf16* wh = sym_b(g_wh);
    bf16* wl = sym_b(g_wl);
    bf16 *lnh = sym_b(g_lnp_h), *lnl = sym_b(g_lnp_l);
    bf16 *ath = sym_b(g_attnp_h), *atl = sym_b(g_attnp_l);
    bf16 *hph = sym_b(g_hp_h), *hpl = sym_b(g_hp_l);
    bf16 *x4h = sym_b(g_x4p_h), *x4l = sym_b(g_x4p_l);

    // ===== weight splits (once per launch) =====
    launch_split(qkv_wa, wh + OFF_QKVA, wl + OFF_QKVA, WQKV);
    launch_split(proj_wa, wh + OFF_PROJA, wl + OFF_PROJA, WPROJ);
    launch_split(fc1_w, wh + OFF_FC1, wl + OFF_FC1, WFC);
    launch_split(fc2_w, wh + OFF_FC2, wl + OFF_FC2, WFC);
    launch_split(qkv_wb, wh + OFF_QKVB, wl + OFF_QKVB, WQKV);
    launch_split(proj_wb, wh + OFF_PROJB, wl + OFF_PROJB, WPROJ);
    launch_split(w1, wh + OFF_W1, wl + OFF_W1, WW1);
    launch_split(w2, wh + OFF_W2, wl + OFF_W2, WW2);
    launch_split(head_w, wh + OFF_HEAD, wl + OFF_HEAD, WHEAD);

    dim3 sc_grid(13, 13, BH), sc_blk(16, 16);
    dim3 av_grid(BH, (NSEQ + 3) / 4), av_blk(64, 4);

    // ===== dense block A =====
    ln_kernel<<<TOKENS, 256>>>(x, ln1a_w, ln1a_b, ln_buf, lnh, lnl);
    launch_gemm(lnh, lnl, wh + OFF_QKVA, wl + OFF_QKVA, qkv, nullptr, nullptr,
                TOKENS, 3 * DMODEL, DMODEL, qkv_ba, nullptr, nullptr, 0, 0);
    attn_scores_kernel<<<sc_grid, sc_blk>>>(qkv, S);
    softmax_kernel<<<BH * NSEQ, 128>>>(S);
    attn_av_kernel<<<av_grid, av_blk>>>(S, qkv, ath, atl);
    launch_gemm(ath, atl, wh + OFF_PROJA, wl + OFF_PROJA, x1, nullptr, nullptr,
                TOKENS, DMODEL, DMODEL, proj_ba, x, nullptr, 0, 0);

    ln_kernel<<<TOKENS, 256>>>(x1, ln2a_w, ln2a_b, ln_buf, lnh, lnl);
    launch_gemm(lnh, lnl, wh + OFF_FC1, wl + OFF_FC1, nullptr, hph, hpl,
                TOKENS, HID, DMODEL, fc1_b, nullptr, nullptr, 0, FLAG_GELU);
    launch_gemm(hph, hpl, wh + OFF_FC2, wl + OFF_FC2, x2, nullptr, nullptr,
                TOKENS, DMODEL, HID, fc2_b, x1, nullptr, 0, 0);

    // ===== MoE block B: attention =====
    ln_kernel<<<TOKENS, 256>>>(x2, ln1b_w, ln1b_b, ln_buf, lnh, lnl);
    launch_gemm(lnh, lnl, wh + OFF_QKVB, wl + OFF_QKVB, qkv, nullptr, nullptr,
                TOKENS, 3 * DMODEL, DMODEL, qkv_bb, nullptr, nullptr, 0, 0);
    attn_scores_kernel<<<sc_grid, sc_blk>>>(qkv, S);
    softmax_kernel<<<BH * NSEQ, 128>>>(S);
    attn_av_kernel<<<av_grid, av_blk>>>(S, qkv, ath, atl);
    launch_gemm(ath, atl, wh + OFF_PROJB, wl + OFF_PROJB, x3, nullptr, nullptr,
                TOKENS, DMODEL, DMODEL, proj_bb, x2, nullptr, 0, 0);

    // ===== MoE FFN: top-4 gathered experts =====
    ln_kernel<<<TOKENS, 256>>>(x3, ln2b_w, ln2b_b, ln_buf, lnh, lnl);
    gate_kernel<<<TOKENS, 256>>>(ln_buf, gate_w, combine);
    zero_counts_kernel<<<1, 32>>>(ecount);
    build_lists_kernel<<<(TOKENS + 255) / 256, 256>>>(combine, ecount, eidx);
    zero_kernel<<<(TOKENS * DMODEL + 255) / 256, 256>>>(ybuf, TOKENS * DMODEL);
    for (int e = 0; e < NEXP; e++) {
        const int* idx_e = eidx + (size_t)e * TOKENS;
        const int* cnt_e = ecount + e;
        launch_gemm(lnh, lnl, wh + OFF_W1 + (size_t)e * WFC, wl + OFF_W1 + (size_t)e * WFC,
                    nullptr, hph, hpl, TOKENS, HID, DMODEL,
                    b1 + (size_t)e * HID, nullptr, nullptr, 0,
                    FLAG_GELU | FLAG_GATHER, idx_e, cnt_e);
        launch_gemm(hph, hpl, wh + OFF_W2 + (size_t)e * WFC, wl + OFF_W2 + (size_t)e * WFC,
                    ybuf, nullptr, nullptr, TOKENS, DMODEL, HID,
                    b2 + (size_t)e * DMODEL, nullptr, combine + e, NEXP,
                    FLAG_ACC | FLAG_SCATTER, idx_e, cnt_e);
    }
    add_split_kernel<<<(TOKENS * DMODEL + 255) / 256, 256>>>(x3, ybuf, x4h, x4l, TOKENS * DMODEL);

    // ===== task heads + masked aggregation =====
    detect_mask_kernel<<<1, 256>>>((const unsigned int*)smask, (NTASK * TOKENS) / 4);
    valid_kernel<<<(TOKENS + 255) / 256, 256>>>(smask, amask, validf, cnt);
    zero_kernel<<<(TOKENS * DMODEL + 255) / 256, 256>>>(sumbuf, TOKENS * DMODEL);
    for (int t = 0; t < NTASK; t++) {
        launch_gemm(x4h, x4l, wh + OFF_HEAD + (size_t)t * WPROJ, wl + OFF_HEAD + (size_t)t * WPROJ,
                    sumbuf, nullptr, nullptr, TOKENS, DMODEL, DMODEL,
                    head_b + (size_t)t * DMODEL, nullptr, validf + (size_t)t * TOKENS, 1, FLAG_ACC);
    }
    final_kernel<<<(TOKENS * DMODEL + 255) / 256, 256>>>(sumbuf, cnt, out);
}

// round 14
// speedup vs baseline: 5.3683x; 1.8187x over previous
#include <cuda_runtime.h>
#include <cuda_bf16.h>
#include <math.h>
#include <stdint.h>

#define TOKENS 1576
#define DMODEL 768
#define HID 3072
#define NHEAD 12
#define HD 64
#define NSEQ 197
#define BATCH 8
#define NEXP 8
#define NTASK 8
#define BH (BATCH*NHEAD)
#define TD (TOKENS*DMODEL)

#define FLAG_GELU    1
#define FLAG_ACC     2
#define FLAG_GATHER  4
#define FLAG_SCATTER 8

typedef __nv_bfloat16 bf16;

// ---------------- fp32 scratch ----------------
__device__ __align__(16) float g_ln[TD];
__device__ __align__(16) float g_qkv[TOKENS*3*DMODEL];
__device__ __align__(16) float g_S[BH*NSEQ*NSEQ];
__device__ __align__(16) float g_x1[TD];
__device__ __align__(16) float g_x2[TD];
__device__ __align__(16) float g_x3[TD];
__device__ __align__(16) float g_slices[NEXP*TD];     // per-expert fc2 out / per-task head out
__device__ __align__(16) float g_combine[TOKENS*NEXP];
__device__ __align__(16) float g_validf[NTASK*TOKENS];
__device__ __align__(16) float g_cnt[TOKENS];
__device__ int g_mask_dt[1];
__device__ int g_ecount[NEXP];
__device__ int g_eidx[NEXP][TOKENS];

// ---------------- bf16 hi/lo plane arenas ----------------
#define WQKV  (768*2304)
#define WPROJ (768*768)
#define WFC   (768*3072)
#define WW1   (8*768*3072)
#define WW2   (8*3072*768)
#define WHEAD (8*768*768)
#define OFF_QKVA  ((size_t)0)
#define OFF_PROJA (OFF_QKVA + WQKV)
#define OFF_FC1   (OFF_PROJA + WPROJ)
#define OFF_FC2   (OFF_FC1 + WFC)
#define OFF_QKVB  (OFF_FC2 + WFC)
#define OFF_PROJB (OFF_QKVB + WQKV)
#define OFF_W1    (OFF_PROJB + WPROJ)
#define OFF_W2    (OFF_W1 + WW1)
#define OFF_HEAD  (OFF_W2 + WW2)
#define TOTALW    (OFF_HEAD + WHEAD)

__device__ __align__(16) bf16 g_wh[TOTALW];
__device__ __align__(16) bf16 g_wl[TOTALW];
__device__ __align__(16) bf16 g_lnp_h[TD];
__device__ __align__(16) bf16 g_lnp_l[TD];
__device__ __align__(16) bf16 g_attnp_h[TD];
__device__ __align__(16) bf16 g_attnp_l[TD];
__device__ __align__(16) bf16 g_hp_h[(size_t)NEXP*TOKENS*HID];  // z-sliced (dense MLP uses slice 0)
__device__ __align__(16) bf16 g_hp_l[(size_t)NEXP*TOKENS*HID];
__device__ __align__(16) bf16 g_x4p_h[TD];
__device__ __align__(16) bf16 g_x4p_l[TD];

__device__ __forceinline__ float gelu_f(float x) {
    return 0.5f * x * (1.0f + erff(x * 0.70710678118654752440f));
}
__device__ __forceinline__ void split_store(float v, bf16* h, bf16* l, size_t idx) {
    bf16 hb = __float2bfloat16_rn(v);
    h[idx] = hb;
    l[idx] = __float2bfloat16_rn(v - __bfloat162float(hb));
}

__device__ __forceinline__ void mma_bf16(float& c0, float& c1, float& c2, float& c3,
                                         uint32_t a0, uint32_t a1, uint32_t a2, uint32_t a3,
                                         uint32_t b0, uint32_t b1) {
    asm volatile(
        "mma.sync.aligned.m16n8k16.row.col.f32.bf16.bf16.f32 "
        "{%0,%1,%2,%3}, {%4,%5,%6,%7}, {%8,%9}, {%0,%1,%2,%3};"
        : "+f"(c0), "+f"(c1), "+f"(c2), "+f"(c3)
        : "r"(a0), "r"(a1), "r"(a2), "r"(a3), "r"(b0), "r"(b1));
}
#define LDSM_X4(r0,r1,r2,r3,addr) \
    asm volatile("ldmatrix.sync.aligned.m8n8.x4.shared.b16 {%0,%1,%2,%3}, [%4];" \
        : "=r"(r0),"=r"(r1),"=r"(r2),"=r"(r3) : "r"(addr))
#define LDSM_X4_T(r0,r1,r2,r3,addr) \
    asm volatile("ldmatrix.sync.aligned.m8n8.x4.trans.shared.b16 {%0,%1,%2,%3}, [%4];" \
        : "=r"(r0),"=r"(r1),"=r"(r2),"=r"(r3) : "r"(addr))
__device__ __forceinline__ void cp16(uint32_t dst, const void* src, int bytes) {
    asm volatile("cp.async.cg.shared.global [%0], [%1], 16, %2;"
                 :: "r"(dst), "l"(src), "r"(bytes));
}
#define CP_COMMIT() asm volatile("cp.async.commit_group;" ::: "memory")
#define CP_WAIT1()  asm volatile("cp.async.wait_group 1;" ::: "memory")
#define CP_WAIT0()  asm volatile("cp.async.wait_group 0;" ::: "memory")

// ---------------- weight split ----------------
__global__ void split_kernel(const float4* __restrict__ src, bf16* __restrict__ h,
                             bf16* __restrict__ l, int n4) {
    int i = blockIdx.x * 256 + threadIdx.x;
    if (i >= n4) return;
    float4 v = src[i];
    float vs[4] = {v.x, v.y, v.z, v.w};
    ushort hh[4], ll[4];
#pragma unroll
    for (int k = 0; k < 4; k++) {
        bf16 hb = __float2bfloat16_rn(vs[k]);
        bf16 lb = __float2bfloat16_rn(vs[k] - __bfloat162float(hb));
        hh[k] = __bfloat16_as_ushort(hb);
        ll[k] = __bfloat16_as_ushort(lb);
    }
    uint2 ph = make_uint2(((uint32_t)hh[1] << 16) | hh[0], ((uint32_t)hh[3] << 16) | hh[2]);
    uint2 pl = make_uint2(((uint32_t)ll[1] << 16) | ll[0], ((uint32_t)ll[3] << 16) | ll[2]);
    reinterpret_cast<uint2*>(h)[i] = ph;
    reinterpret_cast<uint2*>(l)[i] = pl;
}

// ---------------- LayerNorm (fp32 out + split planes) ----------------
__global__ void ln_kernel(const float* __restrict__ x, const float* __restrict__ w,
                          const float* __restrict__ b, float* __restrict__ y,
                          bf16* __restrict__ yh, bf16* __restrict__ yl) {
    int row = blockIdx.x;
    const float* xr = x + (size_t)row * DMODEL;
    __shared__ float red[256];
    int tid = threadIdx.x;

    float s = 0.f;
    for (int i = tid; i < DMODEL; i += 256) s += xr[i];
    red[tid] = s; __syncthreads();
    for (int o = 128; o > 0; o >>= 1) { if (tid < o) red[tid] += red[tid + o]; __syncthreads(); }
    float mean = red[0] * (1.0f / DMODEL);
    __syncthreads();

    float v = 0.f;
    for (int i = tid; i < DMODEL; i += 256) { float d = xr[i] - mean; v += d * d; }
    red[tid] = v; __syncthreads();
    for (int o = 128; o > 0; o >>= 1) { if (tid < o) red[tid] += red[tid + o]; __syncthreads(); }
    float rstd = rsqrtf(red[0] * (1.0f / DMODEL) + 1e-5f);

    for (int i = tid; i < DMODEL; i += 256) {
        float val = (xr[i] - mean) * rstd * w[i] + b[i];
        y[(size_t)row * DMODEL + i] = val;
        split_store(val, yh, yl, (size_t)row * DMODEL + i);
    }
}

// ======== split-bf16 tensor GEMM: 128x128x32, cp.async 2-stage, ldmatrix ========
// Batched over blockIdx.z via per-operand z-strides. C = epi(A@B).
#define ASTR 40
#define BSTR 136
#define APL 5120
#define BPL 4352
#define SMEM_BYTES (2*2*APL*2 + 2*2*BPL*2)   // 75776

__global__ __launch_bounds__(256) void gemm2_kernel(
    const bf16* __restrict__ Ah, const bf16* __restrict__ Al, size_t a_z,
    const bf16* __restrict__ Bh, const bf16* __restrict__ Bl, size_t b_z,
    float* __restrict__ C, size_t c_z,
    bf16* __restrict__ Ch, bf16* __restrict__ Cl, size_t ch_z,
    int M, int N, int K,
    const float* __restrict__ bias, int bias_z,
    const float* __restrict__ residual,
    const float* __restrict__ rowscale, int rs_stride, int rs_z,
    int flags, const int* __restrict__ rowidx, int idx_z,
    const int* __restrict__ count_ptr)
{
    int z = blockIdx.z;
    Ah += (size_t)z * a_z; Al += (size_t)z * a_z;
    Bh += (size_t)z * b_z; Bl += (size_t)z * b_z;
    if (C)  C  += (size_t)z * c_z;
    if (Ch) { Ch += (size_t)z * ch_z; Cl += (size_t)z * ch_z; }
    if (bias) bias += (size_t)z * bias_z;
    if (rowscale) rowscale += (size_t)z * rs_z;
    if (rowidx) rowidx += (size_t)z * idx_z;
    if (count_ptr) M = count_ptr[z];

    int row0 = blockIdx.y * 128, col0 = blockIdx.x * 128;
    if (row0 >= M) return;

    extern __shared__ char smem[];
    uint32_t sbase = (uint32_t)__cvta_generic_to_shared(smem);

    int tid = threadIdx.x;
    int lane = tid & 31;
    int warp = tid >> 5;
    int grp = lane >> 2, tg = lane & 3;
    int warp_m = (warp & 1) * 64;
    int warp_n = (warp >> 1) * 32;

    int a_pl[4], a_r[4], a_c[4], a_src[4], a_sz[4];
#pragma unroll
    for (int s = 0; s < 4; s++) {
        int cid = tid + 256 * s;
        a_pl[s] = cid >> 9; a_r[s] = (cid >> 2) & 127; a_c[s] = cid & 3;
        int gr = row0 + a_r[s];
        bool valid = gr < M;
        a_src[s] = valid ? ((flags & FLAG_GATHER) ? rowidx[gr] : gr) : 0;
        a_sz[s] = valid ? 16 : 0;
    }
    int b_pl[4], b_r[4], b_c[4];
#pragma unroll
    for (int s = 0; s < 4; s++) {
        int cid = tid + 256 * s;
        b_pl[s] = cid >> 9; b_r[s] = (cid >> 4) & 31; b_c[s] = cid & 15;
    }

    auto load_stage = [&](int k0, int stage) {
#pragma unroll
        for (int s = 0; s < 4; s++) {
            const bf16* base = a_pl[s] ? Al : Ah;
            uint32_t dst = sbase + (uint32_t)(stage * 2 + a_pl[s]) * (APL * 2)
                         + (uint32_t)(a_r[s] * ASTR + a_c[s] * 8) * 2;
            cp16(dst, base + (size_t)a_src[s] * K + k0 + a_c[s] * 8, a_sz[s]);
        }
#pragma unroll
        for (int s = 0; s < 4; s++) {
            const bf16* base = b_pl[s] ? Bl : Bh;
            uint32_t dst = sbase + (uint32_t)(2 * 2 * APL * 2)
                         + (uint32_t)(stage * 2 + b_pl[s]) * (BPL * 2)
                         + (uint32_t)(b_r[s] * BSTR + b_c[s] * 8) * 2;
            cp16(dst, base + (size_t)(k0 + b_r[s]) * N + col0 + b_c[s] * 8, 16);
        }
    };

    float acc[4][4][4];
#pragma unroll
    for (int i = 0; i < 4; i++)
#pragma unroll
        for (int j = 0; j < 4; j++)
#pragma unroll
            for (int r = 0; r < 4; r++) acc[i][j][r] = 0.f;

    int nK = K / 32;
    load_stage(0, 0);
    CP_COMMIT();

    for (int kt = 0; kt < nK; kt++) {
        int buf = kt & 1;
        if (kt + 1 < nK) {
            load_stage((kt + 1) * 32, buf ^ 1);
            CP_COMMIT();
            CP_WAIT1();
        } else {
            CP_WAIT0();
        }
        __syncthreads();

        uint32_t aBaseH = sbase + (uint32_t)(buf * 2 + 0) * (APL * 2);
        uint32_t aBaseL = sbase + (uint32_t)(buf * 2 + 1) * (APL * 2);
        uint32_t bBaseH = sbase + (uint32_t)(2 * 2 * APL * 2) + (uint32_t)(buf * 2 + 0) * (BPL * 2);
        uint32_t bBaseL = sbase + (uint32_t)(2 * 2 * APL * 2) + (uint32_t)(buf * 2 + 1) * (BPL * 2);

#pragma unroll
        for (int kb = 0; kb < 32; kb += 16) {
            uint32_t bh[4][2], bl[4][2];
#pragma unroll
            for (int jj = 0; jj < 2; jj++) {
                int rowk = kb + (lane & 7) + ((lane >> 3) & 1) * 8;
                int coln = warp_n + jj * 16 + (lane >> 4) * 8;
                uint32_t off = (uint32_t)(rowk * BSTR + coln) * 2;
                LDSM_X4_T(bh[2*jj][0], bh[2*jj][1], bh[2*jj+1][0], bh[2*jj+1][1], bBaseH + off);
                LDSM_X4_T(bl[2*jj][0], bl[2*jj][1], bl[2*jj+1][0], bl[2*jj+1][1], bBaseL + off);
            }
#pragma unroll
            for (int i = 0; i < 4; i++) {
                int rowm = warp_m + i * 16 + (lane & 15);
                int colk = kb + (lane >> 4) * 8;
                uint32_t off = (uint32_t)(rowm * ASTR + colk) * 2;
                uint32_t ah0, ah1, ah2, ah3, al0, al1, al2, al3;
                LDSM_X4(ah0, ah1, ah2, ah3, aBaseH + off);
                LDSM_X4(al0, al1, al2, al3, aBaseL + off);
#pragma unroll
                for (int j = 0; j < 4; j++) {
                    mma_bf16(acc[i][j][0], acc[i][j][1], acc[i][j][2], acc[i][j][3],
                             ah0, ah1, ah2, ah3, bh[j][0], bh[j][1]);
                    mma_bf16(acc[i][j][0], acc[i][j][1], acc[i][j][2], acc[i][j][3],
                             ah0, ah1, ah2, ah3, bl[j][0], bl[j][1]);
                    mma_bf16(acc[i][j][0], acc[i][j][1], acc[i][j][2], acc[i][j][3],
                             al0, al1, al2, al3, bh[j][0], bh[j][1]);
                }
            }
        }
        __syncthreads();
    }

    bool do_gelu = (flags & FLAG_GELU) != 0;
    bool do_acc  = (flags & FLAG_ACC)  != 0;
#pragma unroll
    for (int i = 0; i < 4; i++) {
#pragma unroll
        for (int half = 0; half < 2; half++) {
            int r = row0 + warp_m + i * 16 + grp + half * 8;
            if (r >= M) continue;
            int crow = (flags & FLAG_SCATTER) ? rowidx[r] : r;
            float rs = 1.f;
            if (rowscale) rs = rowscale[(size_t)crow * rs_stride];
#pragma unroll
            for (int j = 0; j < 4; j++) {
#pragma unroll
                for (int s = 0; s < 2; s++) {
                    int c = col0 + warp_n + j * 8 + tg * 2 + s;
                    float v = acc[i][j][half * 2 + s];
                    if (bias) v += bias[c];
                    if (do_gelu) v = gelu_f(v);
                    v *= rs;
                    if (residual) v += residual[(size_t)crow * N + c];
                    size_t idx = (size_t)crow * N + c;
                    if (Ch) split_store(v, Ch, Cl, idx);
                    if (C) { if (do_acc) C[idx] += v; else C[idx] = v; }
                }
            }
        }
    }
}

// ---------------- Attention: scores S[bh,n,m] = (q.k)/8 ----------------
__global__ void attn_scores_kernel(const float* __restrict__ qkv, float* __restrict__ S) {
    int bh = blockIdx.z;
    int b = bh / NHEAD, h = bh % NHEAD;
    int n0 = blockIdx.y * 16, m0 = blockIdx.x * 16;
    __shared__ float Qs[16][65];
    __shared__ float Ks[16][65];
    int tid = threadIdx.y * 16 + threadIdx.x;
    int idx = tid * 4;
    int r = idx >> 6, c = idx & 63;

    if (n0 + r < NSEQ) {
        const float* src = qkv + ((size_t)(b * NSEQ + n0 + r) * 3 + 0) * DMODEL + h * HD + c;
        float4 v = *reinterpret_cast<const float4*>(src);
        Qs[r][c] = v.x; Qs[r][c + 1] = v.y; Qs[r][c + 2] = v.z; Qs[r][c + 3] = v.w;
    } else {
        Qs[r][c] = Qs[r][c + 1] = Qs[r][c + 2] = Qs[r][c + 3] = 0.f;
    }
    if (m0 + r < NSEQ) {
        const float* src = qkv + ((size_t)(b * NSEQ + m0 + r) * 3 + 1) * DMODEL + h * HD + c;
        float4 v = *reinterpret_cast<const float4*>(src);
        Ks[r][c] = v.x; Ks[r][c + 1] = v.y; Ks[r][c + 2] = v.z; Ks[r][c + 3] = v.w;
    } else {
        Ks[r][c] = Ks[r][c + 1] = Ks[r][c + 2] = Ks[r][c + 3] = 0.f;
    }
    __syncthreads();

    int n = n0 + threadIdx.y, m = m0 + threadIdx.x;
    if (n < NSEQ && m < NSEQ) {
        float acc = 0.f;
#pragma unroll
        for (int d = 0; d < HD; d++) acc += Qs[threadIdx.y][d] * Ks[threadIdx.x][d];
        S[((size_t)bh * NSEQ + n) * NSEQ + m] = acc * 0.125f;
    }
}

// ---------------- row softmax over 197 ----------------
__global__ void softmax_kernel(float* __restrict__ S) {
    int row = blockIdx.x;
    float* p = S + (size_t)row * NSEQ;
    __shared__ float red[128];
    int tid = threadIdx.x;

    float m = -1e30f;
    for (int i = tid; i < NSEQ; i += 128) m = fmaxf(m, p[i]);
    red[tid] = m; __syncthreads();
    for (int o = 64; o > 0; o >>= 1) { if (tid < o) red[tid] = fmaxf(red[tid], red[tid + o]); __syncthreads(); }
    m = red[0]; __syncthreads();

    float s = 0.f;
    for (int i = tid; i < NSEQ; i += 128) { float e = __expf(p[i] - m); p[i] = e; s += e; }
    red[tid] = s; __syncthreads();
    for (int o = 64; o > 0; o >>= 1) { if (tid < o) red[tid] += red[tid + o]; __syncthreads(); }
    float inv = 1.0f / red[0];
    for (int i = tid; i < NSEQ; i += 128) p[i] *= inv;
}

// ------------- out planes = split(sum_m P[bh,n,m] * V[b,m,h,d]) -------------
__global__ void attn_av_kernel(const float* __restrict__ S, const float* __restrict__ qkv,
                               bf16* __restrict__ oh, bf16* __restrict__ ol) {
    int bh = blockIdx.x;
    int b = bh / NHEAD, h = bh % NHEAD;
    int n = blockIdx.y * 4 + threadIdx.y;
    int d = threadIdx.x;
    if (n >= NSEQ) return;
    const float* Sr = S + ((size_t)bh * NSEQ + n) * NSEQ;
    float acc = 0.f;
    for (int m = 0; m < NSEQ; m++)
        acc += Sr[m] * qkv[((size_t)(b * NSEQ + m) * 3 + 2) * DMODEL + h * HD + d];
    split_store(acc, oh, ol, (size_t)(b * NSEQ + n) * DMODEL + h * HD + d);
}

// ---------------- MoE gate ----------------
__global__ void gate_kernel(const float* __restrict__ x, const float* __restrict__ gw,
                            float* __restrict__ combine) {
    int token = blockIdx.x;
    int warp = threadIdx.x / 32, lane = threadIdx.x % 32;
    const float* xr = x + (size_t)token * DMODEL;
    float acc = 0.f;
    for (int d = lane; d < DMODEL; d += 32) acc += xr[d] * gw[(size_t)d * NEXP + warp];
#pragma unroll
    for (int o = 16; o > 0; o >>= 1) acc += __shfl_down_sync(0xffffffffu, acc, o);
    __shared__ float lg[NEXP];
    if (lane == 0) lg[warp] = acc;
    __syncthreads();
    if (threadIdx.x == 0) {
        float mx = lg[0];
        for (int e = 1; e < NEXP; e++) mx = fmaxf(mx, lg[e]);
        float p[NEXP]; float se = 0.f;
        for (int e = 0; e < NEXP; e++) { p[e] = __expf(lg[e] - mx); se += p[e]; }
        float inv = 1.0f / se;
        for (int e = 0; e < NEXP; e++) p[e] *= inv;
        float outv[NEXP]; bool used[NEXP];
        for (int e = 0; e < NEXP; e++) { outv[e] = 0.f; used[e] = false; }
        for (int k = 0; k < 4; k++) {
            int best = -1; float bv = -1.f;
            for (int e = 0; e < NEXP; e++)
                if (!used[e] && p[e] > bv) { bv = p[e]; best = e; }
            used[best] = true; outv[best] = bv;
        }
        for (int e = 0; e < NEXP; e++) combine[(size_t)token * NEXP + e] = outv[e];
    }
}

__global__ void zero_counts_kernel(int* __restrict__ ecount) {
    if (threadIdx.x < NEXP) ecount[threadIdx.x] = 0;
}
__global__ void build_lists_kernel(const float* __restrict__ combine,
                                   int* __restrict__ ecount, int* __restrict__ eidx) {
    int t = blockIdx.x * blockDim.x + threadIdx.x;
    if (t >= TOKENS) return;
#pragma unroll
    for (int e = 0; e < NEXP; e++) {
        if (combine[(size_t)t * NEXP + e] > 0.f) {
            int pos = atomicAdd(&ecount[e], 1);
            eidx[(size_t)e * TOKENS + pos] = t;
        }
    }
}

__global__ void zero4_kernel(float4* __restrict__ p, int n4) {
    int i = blockIdx.x * blockDim.x + threadIdx.x;
    if (i < n4) p[i] = make_float4(0.f, 0.f, 0.f, 0.f);
}

// x4 planes = split(x3 + sum_z slices[z])
__global__ void moe_combine_kernel(const float* __restrict__ x3, const float* __restrict__ slices,
                                   bf16* __restrict__ oh, bf16* __restrict__ ol) {
    int i = blockIdx.x * blockDim.x + threadIdx.x;
    if (i >= TD) return;
    float s = x3[i];
#pragma unroll
    for (int z = 0; z < NEXP; z++) s += slices[(size_t)z * TD + i];
    split_store(s, oh, ol, i);
}

// out = (sum_z slices[z]) / (cnt + 1e-6)
__global__ void final2_kernel(const float* __restrict__ slices, const float* __restrict__ cnt,
                              float* __restrict__ out) {
    int i = blockIdx.x * blockDim.x + threadIdx.x;
    if (i >= TD) return;
    float s = 0.f;
#pragma unroll
    for (int z = 0; z < NTASK; z++) s += slices[(size_t)z * TD + i];
    out[i] = s / (cnt[i / DMODEL] + 1e-6f);
}

// ---------------- mask dtype sniffing ----------------
__global__ void detect_mask_kernel(const unsigned int* __restrict__ w, int nwords) {
    __shared__ int flags[2];
    if (threadIdx.x < 2) flags[threadIdx.x] = 0;
    __syncthreads();
    int ni = 0, nf = 0;
    for (int i = threadIdx.x; i < nwords; i += blockDim.x) {
        unsigned v = w[i];
        if (v > 1u) ni = 1;
        if (v != 0u && v != 0x3F800000u) nf = 1;
    }
    if (ni) flags[0] = 1;
    if (nf) flags[1] = 1;
    __syncthreads();
    if (threadIdx.x == 0)
        g_mask_dt[0] = (!flags[0]) ? 0 : ((!flags[1]) ? 1 : 2);
}
__device__ __forceinline__ float read_mask(const void* p, size_t idx, int dt) {
    if (dt == 0) return ((const int*)p)[idx] ? 1.f : 0.f;
    if (dt == 1) return ((const float*)p)[idx] != 0.f ? 1.f : 0.f;
    return ((const unsigned char*)p)[idx] ? 1.f : 0.f;
}
__global__ void valid_kernel(const void* __restrict__ sm, const void* __restrict__ am,
                             float* __restrict__ validf, float* __restrict__ cnt) {
    int t = blockIdx.x * blockDim.x + threadIdx.x;
    if (t >= TOKENS) return;
    int dt = g_mask_dt[0];
    float a = read_mask(am, t, dt);
    float c = 0.f;
    for (int k = 0; k < NTASK; k++) {
        float v = read_mask(sm, (size_t)k * TOKENS + t, dt) * a;
        validf[(size_t)k * TOKENS + t] = v;
        c += v;
    }
    cnt[t] = c;
}

// ---------------- host orchestration ----------------
static float* sym_f(const void* s) { void* p = nullptr; cudaGetSymbolAddress(&p, s); return (float*)p; }
static int*   sym_i(const void* s) { void* p = nullptr; cudaGetSymbolAddress(&p, s); return (int*)p; }
static bf16*  sym_b(const void* s) { void* p = nullptr; cudaGetSymbolAddress(&p, s); return (bf16*)p; }

static void launch_split(const float* src, bf16* h, bf16* l, size_t n) {
    int n4 = (int)(n / 4);
    split_kernel<<<(n4 + 255) / 256, 256>>>((const float4*)src, h, l, n4);
}

static void launch_gemm(dim3 grid,
                        const bf16* Ah, const bf16* Al, size_t a_z,
                        const bf16* Bh, const bf16* Bl, size_t b_z,
                        float* C, size_t c_z, bf16* Ch, bf16* Cl, size_t ch_z,
                        int M, int N, int K,
                        const float* bias, int bias_z,
                        const float* residual,
                        const float* rowscale, int rs_stride, int rs_z,
                        int flags, const int* rowidx, int idx_z,
                        const int* count_ptr) {
    gemm2_kernel<<<grid, 256, SMEM_BYTES>>>(Ah, Al, a_z, Bh, Bl, b_z, C, c_z, Ch, Cl, ch_z,
                                            M, N, K, bias, bias_z, residual,
                                            rowscale, rs_stride, rs_z, flags,
                                            rowidx, idx_z, count_ptr);
}

extern "C" void kernel_launch(void* const* d_in, const int* in_sizes, int n_in,
                              void* d_out, int out_size) {
    const float* x       = (const float*)d_in[0];
    const float* ln1a_w  = (const float*)d_in[1];
    const float* ln1a_b  = (const float*)d_in[2];
    const float* qkv_wa  = (const float*)d_in[3];
    const float* qkv_ba  = (const float*)d_in[4];
    const float* proj_wa = (const float*)d_in[5];
    const float* proj_ba = (const float*)d_in[6];
    const float* ln2a_w  = (const float*)d_in[7];
    const float* ln2a_b  = (const float*)d_in[8];
    const float* fc1_w   = (const float*)d_in[9];
    const float* fc1_b   = (const float*)d_in[10];
    const float* fc2_w   = (const float*)d_in[11];
    const float* fc2_b   = (const float*)d_in[12];
    const float* ln1b_w  = (const float*)d_in[13];
    const float* ln1b_b  = (const float*)d_in[14];
    const float* qkv_wb  = (const float*)d_in[15];
    const float* qkv_bb  = (const float*)d_in[16];
    const float* proj_wb = (const float*)d_in[17];
    const float* proj_bb = (const float*)d_in[18];
    const float* ln2b_w  = (const float*)d_in[19];
    const float* ln2b_b  = (const float*)d_in[20];
    const float* gate_w  = (const float*)d_in[21];
    const float* w1      = (const float*)d_in[22];
    const float* b1      = (const float*)d_in[23];
    const float* w2      = (const float*)d_in[24];
    const float* b2      = (const float*)d_in[25];
    const float* head_w  = (const float*)d_in[26];
    const float* head_b  = (const float*)d_in[27];
    const void*  smask   = d_in[28];
    const void*  amask   = d_in[29];
    float* out = (float*)d_out;

    cudaFuncSetAttribute(gemm2_kernel, cudaFuncAttributeMaxDynamicSharedMemorySize, SMEM_BYTES);

    float* ln_buf  = sym_f(g_ln);
    float* qkv     = sym_f(g_qkv);
    float* S       = sym_f(g_S);
    float* x1      = sym_f(g_x1);
    float* x2      = sym_f(g_x2);
    float* x3      = sym_f(g_x3);
    float* slices  = sym_f(g_slices);
    float* combine = sym_f(g_combine);
    float* validf  = sym_f(g_validf);
    float* cnt     = sym_f(g_cnt);
    int*   ecount  = sym_i(g_ecount);
    int*   eidx    = sym_i(g_eidx);

    bf16* wh = sym_b(g_wh);
    bf16* wl = sym_b(g_wl);
    bf16 *lnh = sym_b(g_lnp_h), *lnl = sym_b(g_lnp_l);
    bf16 *ath = sym_b(g_attnp_h), *atl = sym_b(g_attnp_l);
    bf16 *hph = sym_b(g_hp_h), *hpl = sym_b(g_hp_l);
    bf16 *x4h = sym_b(g_x4p_h), *x4l = sym_b(g_x4p_l);

    // ===== weight splits (once per launch) =====
    launch_split(qkv_wa, wh + OFF_QKVA, wl + OFF_QKVA, WQKV);
    launch_split(proj_wa, wh + OFF_PROJA, wl + OFF_PROJA, WPROJ);
    launch_split(fc1_w, wh + OFF_FC1, wl + OFF_FC1, WFC);
    launch_split(fc2_w, wh + OFF_FC2, wl + OFF_FC2, WFC);
    launch_split(qkv_wb, wh + OFF_QKVB, wl + OFF_QKVB, WQKV);
    launch_split(proj_wb, wh + OFF_PROJB, wl + OFF_PROJB, WPROJ);
    launch_split(w1, wh + OFF_W1, wl + OFF_W1, WW1);
    launch_split(w2, wh + OFF_W2, wl + OFF_W2, WW2);
    launch_split(head_w, wh + OFF_HEAD, wl + OFF_HEAD, WHEAD);

    dim3 sc_grid(13, 13, BH), sc_blk(16, 16);
    dim3 av_grid(BH, (NSEQ + 3) / 4), av_blk(64, 4);

    // ===== dense block A =====
    ln_kernel<<<TOKENS, 256>>>(x, ln1a_w, ln1a_b, ln_buf, lnh, lnl);
    launch_gemm(dim3(18, 13, 1), lnh, lnl, 0, wh + OFF_QKVA, wl + OFF_QKVA, 0,
                qkv, 0, nullptr, nullptr, 0, TOKENS, 3 * DMODEL, DMODEL,
                qkv_ba, 0, nullptr, nullptr, 0, 0, 0, nullptr, 0, nullptr);
    attn_scores_kernel<<<sc_grid, sc_blk>>>(qkv, S);
    softmax_kernel<<<BH * NSEQ, 128>>>(S);
    attn_av_kernel<<<av_grid, av_blk>>>(S, qkv, ath, atl);
    launch_gemm(dim3(6, 13, 1), ath, atl, 0, wh + OFF_PROJA, wl + OFF_PROJA, 0,
                x1, 0, nullptr, nullptr, 0, TOKENS, DMODEL, DMODEL,
                proj_ba, 0, x, nullptr, 0, 0, 0, nullptr, 0, nullptr);

    ln_kernel<<<TOKENS, 256>>>(x1, ln2a_w, ln2a_b, ln_buf, lnh, lnl);
    launch_gemm(dim3(24, 13, 1), lnh, lnl, 0, wh + OFF_FC1, wl + OFF_FC1, 0,
                nullptr, 0, hph, hpl, 0, TOKENS, HID, DMODEL,
                fc1_b, 0, nullptr, nullptr, 0, 0, FLAG_GELU, nullptr, 0, nullptr);
    launch_gemm(dim3(6, 13, 1), hph, hpl, 0, wh + OFF_FC2, wl + OFF_FC2, 0,
                x2, 0, nullptr, nullptr, 0, TOKENS, DMODEL, HID,
                fc2_b, 0, x1, nullptr, 0, 0, 0, nullptr, 0, nullptr);

    // ===== MoE block B: attention =====
    ln_kernel<<<TOKENS, 256>>>(x2, ln1b_w, ln1b_b, ln_buf, lnh, lnl);
    launch_gemm(dim3(18, 13, 1), lnh, lnl, 0, wh + OFF_QKVB, wl + OFF_QKVB, 0,
                qkv, 0, nullptr, nullptr, 0, TOKENS, 3 * DMODEL, DMODEL,
                qkv_bb, 0, nullptr, nullptr, 0, 0, 0, nullptr, 0, nullptr);
    attn_scores_kernel<<<sc_grid, sc_blk>>>(qkv, S);
    softmax_kernel<<<BH * NSEQ, 128>>>(S);
    attn_av_kernel<<<av_grid, av_blk>>>(S, qkv, ath, atl);
    launch_gemm(dim3(6, 13, 1), ath, atl, 0, wh + OFF_PROJB, wl + OFF_PROJB, 0,
                x3, 0, nullptr, nullptr, 0, TOKENS, DMODEL, DMODEL,
                proj_bb, 0, x2, nullptr, 0, 0, 0, nullptr, 0, nullptr);

    // ===== MoE FFN: batched top-4 experts (z = expert) =====
    ln_kernel<<<TOKENS, 256>>>(x3, ln2b_w, ln2b_b, ln_buf, lnh, lnl);
    gate_kernel<<<TOKENS, 256>>>(ln_buf, gate_w, combine);
    zero_counts_kernel<<<1, 32>>>(ecount);
    build_lists_kernel<<<(TOKENS + 255) / 256, 256>>>(combine, ecount, eidx);
    zero4_kernel<<<(NEXP * TD / 4 + 255) / 256, 256>>>((float4*)slices, NEXP * TD / 4);

    // fc1: gather tokens per expert -> compact GELU planes per expert slice
    launch_gemm(dim3(24, 13, NEXP), lnh, lnl, 0, wh + OFF_W1, wl + OFF_W1, WFC,
                nullptr, 0, hph, hpl, (size_t)TOKENS * HID, TOKENS, HID, DMODEL,
                b1, HID, nullptr, nullptr, 0, 0,
                FLAG_GELU | FLAG_GATHER, eidx, TOKENS, ecount);
    // fc2: compact input -> scatter combine-scaled rows into private slice per expert
    launch_gemm(dim3(6, 13, NEXP), hph, hpl, (size_t)TOKENS * HID, wh + OFF_W2, wl + OFF_W2, WFC,
                slices, TD, nullptr, nullptr, 0, TOKENS, DMODEL, HID,
                b2, DMODEL, nullptr, combine, NEXP, 1,
                FLAG_SCATTER, eidx, TOKENS, ecount);
    moe_combine_kernel<<<(TD + 255) / 256, 256>>>(x3, slices, x4h, x4l);

    // ===== task heads (z = task) + masked aggregation =====
    detect_mask_kernel<<<1, 256>>>((const unsigned int*)smask, (NTASK * TOKENS) / 4);
    valid_kernel<<<(TOKENS + 255) / 256, 256>>>(smask, amask, validf, cnt);
    launch_gemm(dim3(6, 13, NTASK), x4h, x4l, 0, wh + OFF_HEAD, wl + OFF_HEAD, WPROJ,
                slices, TD, nullptr, nullptr, 0, TOKENS, DMODEL, DMODEL,
                head_b, DMODEL, nullptr, validf, 1, TOKENS,
                0, nullptr, 0, nullptr);
    final2_kernel<<<(TD + 255) / 256, 256>>>(slices, cnt, out);
}